// round 12
// baseline (speedup 1.0000x reference)
#include <cuda_runtime.h>

#define Bq 8
#define Sq 4096
#define Hq 2048               // half period
#define Dq 512
#define Mq 16
#define NCH 64                // chunks for proj/final (pair-rows per chunk = 32)
#define SCH (Hq/NCH)          // 32
#define INV_S (1.0f/4096.0f)

// ---------------- device scratch (no allocations allowed) ----------------
__device__ __align__(16) float2 g_tw[Hq*Mq];   // per (s,k), s<2048: (cos(w_k s), -sin(w_k s))
__device__ float  g_mu[Bq*Sq];
__device__ float  g_rs[Bq*Sq];
__device__ __align__(16) float2 g_part[NCH*Bq*Mq*Dq]; // partial A projections [chunk][b][k][d]
__device__ float2 g_C[Bq*Mq];                  // C_k[b] = sum_s rs*mu*tw  (complex)
__device__ float2 g_D[Bq*Mq*Dq];               // spectral coeffs with w applied [b][k][d]
__device__ float  g_xsf[Bq*Dq];                // xs at s=0   (scaled by 1/S)
__device__ float  g_xsl[Bq*Dq];                // xs at s=S-1 (scaled by 1/S)
__device__ __align__(16) float2 g_A[Bq*Mq*Dq]; // combined scaled coeffs [b][k][d]
__device__ float  g_c0[Bq*Dq];                 // boundary correction at s=0
__device__ float  g_cN[Bq*Dq];                 // boundary correction at s=S-1
// transposed conv weights, [di][dd] layout (coalesced along dd)
__device__ float  g_w1[Dq*Dq];
__device__ float  g_ws[Dq*Dq];                 // w0+w2
__device__ float  g_wd[Dq*Dq];                 // w2-w0
// c1 partials over di-chunks
__device__ float2 g_c1p[4*Bq*Mq*Dq];           // [cc][b][k][dd]
__device__ float2 g_edg[4*Bq*Dq];              // [cc][b][dd] -> (a0, aN)

// ---------------- twiddle table (float sincospi: exact argument) ----------------
__global__ void twiddle_k() {
    int i = blockIdx.x * 256 + threadIdx.x;   // i = s*16 + k, s < 2048
    int s = i >> 4, k = i & 15;
    int ks = (k * s) & (Sq - 1);
    float sf, cf;
    sincospif((float)ks * (1.0f / 2048.0f), &sf, &cf);
    g_tw[i] = make_float2(cf, -sf);
}

// ---------------- transpose conv weights into [di][dd] planes ----------------
__global__ void tr_k(const float* __restrict__ cw) {
    __shared__ float t1[32][33], ts[32][33], td[32][33];
    int di0 = blockIdx.x * 32, dd0 = blockIdx.y * 32;
    int tx = threadIdx.x, ty = threadIdx.y;   // block (32,8)
#pragma unroll
    for (int jj = 0; jj < 4; jj++) {
        int ddl = ty + jj * 8;
        const float* p = cw + ((size_t)(dd0 + ddl) * Dq + di0 + tx) * 3;
        float w0 = p[0], w1 = p[1], w2 = p[2];
        t1[ddl][tx] = w1;
        ts[ddl][tx] = w0 + w2;
        td[ddl][tx] = w2 - w0;
    }
    __syncthreads();
#pragma unroll
    for (int jj = 0; jj < 4; jj++) {
        int dil = ty + jj * 8;
        size_t o = (size_t)(di0 + dil) * Dq + dd0 + tx;
        g_w1[o] = t1[tx][dil];
        g_ws[o] = ts[tx][dil];
        g_wd[o] = td[tx][dil];
    }
}

// ---------------- LayerNorm stats: one warp per (b,s) row ----------------
__global__ void ln_k(const float* __restrict__ x) {
    int lane = threadIdx.x & 31;
    int row  = blockIdx.x * 8 + (threadIdx.x >> 5);   // b*Sq + s
    const float4* xr = (const float4*)(x + (size_t)row * Dq);
    float s1 = 0.f, s2 = 0.f;
#pragma unroll
    for (int it = 0; it < 4; it++) {
        float4 v = xr[lane + it * 32];
        s1 += (v.x + v.y) + (v.z + v.w);
        s2 = fmaf(v.x, v.x, s2); s2 = fmaf(v.y, v.y, s2);
        s2 = fmaf(v.z, v.z, s2); s2 = fmaf(v.w, v.w, s2);
    }
#pragma unroll
    for (int off = 16; off > 0; off >>= 1) {
        s1 += __shfl_xor_sync(0xffffffffu, s1, off);
        s2 += __shfl_xor_sync(0xffffffffu, s2, off);
    }
    if (lane == 0) {
        float mu  = s1 * (1.f / Dq);
        float var = fmaf(-mu, mu, s2 * (1.f / Dq));
        g_mu[row] = mu;
        g_rs[row] = rsqrtf(var + 1e-5f);
    }
}

// ---------------- C_k[b] = sum_s rs*mu*tw (per-batch scalar correction) ----------------
__global__ void cmu_k() {
    int k = blockIdx.x, b = blockIdx.y, t = threadIdx.x;
    float sgn = (k & 1) ? -1.f : 1.f;
    float2 acc = make_float2(0.f, 0.f);
    for (int p = t; p < Hq; p += 256) {
        float ma = g_mu[b * Sq + p]      * g_rs[b * Sq + p];
        float mb = g_mu[b * Sq + Hq + p] * g_rs[b * Sq + Hq + p];
        float m = fmaf(sgn, mb, ma);
        float2 tw = g_tw[p * Mq + k];
        acc.x = fmaf(m, tw.x, acc.x);
        acc.y = fmaf(m, tw.y, acc.y);
    }
    __shared__ float2 red[256];
    red[t] = acc; __syncthreads();
    for (int o = 128; o > 0; o >>= 1) {
        if (t < o) { red[t].x += red[t + o].x; red[t].y += red[t + o].y; }
        __syncthreads();
    }
    if (t == 0) g_C[b * Mq + k] = red[0];
}

// ---------------- projection: A_k[b,d] = sum_s rs*x*tw, 2 d per thread ----------------
// half-period pairing; grid (NCH, Bq), block 256 (each thread owns d=2t, 2t+1)
__global__ void __launch_bounds__(256) proj_k(const float* __restrict__ x) {
    __shared__ ulonglong2 stw[SCH * 8];   // 4 KB
    __shared__ float srs[2 * SCH];
    int b = blockIdx.y, ch = blockIdx.x, t = threadIdx.x;
    int s0 = ch * SCH;
    const ulonglong2* twp = (const ulonglong2*)(g_tw + (size_t)s0 * Mq);
    stw[t] = twp[t];   // 256 entries exactly
    int row0 = b * Sq + s0;
    if (t < 2 * SCH) srs[t] = g_rs[row0 + (t < SCH ? t : Hq + (t - SCH))];
    __syncthreads();

    unsigned long long acc0[Mq], acc1[Mq];
#pragma unroll
    for (int k = 0; k < Mq; k++) { acc0[k] = 0ull; acc1[k] = 0ull; }

    const float2* xa = (const float2*)(x + (size_t)row0 * Dq) + t;   // row stride 256
    const float2* xb = xa + (size_t)Hq * 256;

    float2 va[4], vb[4];
#pragma unroll
    for (int u = 0; u < 4; u++) { va[u] = xa[u * 256]; vb[u] = xb[u * 256]; }

#pragma unroll 1
    for (int i0 = 0; i0 < SCH; i0 += 4) {
        int ip = (i0 + 4 < SCH) ? (i0 + 4) : (SCH - 4);   // clamped prefetch
        float2 na[4], nb[4];
#pragma unroll
        for (int u = 0; u < 4; u++) { na[u] = xa[(ip + u) * 256]; nb[u] = xb[(ip + u) * 256]; }
#pragma unroll
        for (int u = 0; u < 4; u++) {
            int i = i0 + u;
            float rsa = srs[i], rsb = srs[SCH + i];
            float ax = va[u].x * rsa, ay = va[u].y * rsa;
            float bx = vb[u].x * rsb, by = vb[u].y * rsb;
            float ysx = ax + bx, ydx = ax - bx;
            float ysy = ay + by, ydy = ay - by;
            unsigned long long psx, pdx, psy, pdy;
            asm("mov.b64 %0, {%1, %1};" : "=l"(psx) : "f"(ysx));
            asm("mov.b64 %0, {%1, %1};" : "=l"(pdx) : "f"(ydx));
            asm("mov.b64 %0, {%1, %1};" : "=l"(psy) : "f"(ysy));
            asm("mov.b64 %0, {%1, %1};" : "=l"(pdy) : "f"(ydy));
#pragma unroll
            for (int k2 = 0; k2 < 8; k2++) {
                ulonglong2 tt = stw[i * 8 + k2];
                asm("fma.rn.f32x2 %0, %1, %2, %0;" : "+l"(acc0[2*k2  ]) : "l"(psx), "l"(tt.x));
                asm("fma.rn.f32x2 %0, %1, %2, %0;" : "+l"(acc0[2*k2+1]) : "l"(pdx), "l"(tt.y));
                asm("fma.rn.f32x2 %0, %1, %2, %0;" : "+l"(acc1[2*k2  ]) : "l"(psy), "l"(tt.x));
                asm("fma.rn.f32x2 %0, %1, %2, %0;" : "+l"(acc1[2*k2+1]) : "l"(pdy), "l"(tt.y));
            }
        }
#pragma unroll
        for (int u = 0; u < 4; u++) { va[u] = na[u]; vb[u] = nb[u]; }
    }
    ulonglong2* pout = (ulonglong2*)g_part + ((size_t)(ch * Bq + b) * Mq) * 256 + t;
#pragma unroll
    for (int k = 0; k < Mq; k++) pout[k * 256] = make_ulonglong2(acc0[k], acc1[k]);
}

// ---------------- reduce partials, apply LN affine correction + spectral weight ----------------
__global__ void c0a_k(const float* __restrict__ wr, const float* __restrict__ wi,
                      const float* __restrict__ gamma, const float* __restrict__ beta) {
    int k = blockIdx.x, b = blockIdx.y;
    int d = blockIdx.z * 128 + threadIdx.x;
    const unsigned long long* pp = (const unsigned long long*)g_part;
    unsigned long long s = 0ull;
#pragma unroll 8
    for (int c = 0; c < NCH; c++) {
        unsigned long long v = pp[((size_t)(c * Bq + b) * Mq + k) * Dq + d];
        asm("add.rn.f32x2 %0, %0, %1;" : "+l"(s) : "l"(v));
    }
    float sr, si;
    asm("mov.b64 {%0, %1}, %2;" : "=f"(sr), "=f"(si) : "l"(s));
    float2 C = g_C[b * Mq + k];
    float gm = gamma[d], bt = beta[d];
    float Pr = gm * (sr - C.x);
    if (k == 0) Pr += 4096.f * bt;      // T_0 = S, T_k = 0 for k>0
    float Pi = gm * (si - C.y);
    float wrv = wr[d * Mq + k], wiv = wi[d * Mq + k];
    float Dr = Pr * wrv - Pi * wiv;
    float Di = (k == 0) ? 0.f : fmaf(Pr, wiv, Pi * wrv);   // irfft drops Im of bin 0
    g_D[(size_t)(b * Mq + k) * Dq + d] = make_float2(Dr, Di);
}

// ---------------- edge values xs(0), xs(S-1) ----------------
__global__ void c0b_k() {
    int b = blockIdx.x, di = threadIdx.x;
    float xsf = 0.f, xsl = 0.f;
#pragma unroll
    for (int k = 0; k < Mq; k++) {
        float2 Dv = g_D[(size_t)(b * Mq + k) * Dq + di];
        float2 t = g_tw[Mq + k];           // s=1 row: (cos w_k, -sin w_k)
        float ck = t.x, sk = -t.y;
        float m = (k == 0) ? 1.f : 2.f;
        xsf += m * Dv.x;
        xsl += m * (Dv.x * ck + Dv.y * sk);    // Re(D_k e^{-i w_k})
    }
    g_xsf[b * Dq + di] = xsf * INV_S;
    g_xsl[b * Dq + di] = xsl * INV_S;
}

// ---------------- spectral-domain conv partials: coalesced, split over di chunks ----------------
__global__ void c1_k() {
    int kg = blockIdx.x & 3, cc = blockIdx.x >> 2;
    int tile = blockIdx.y, b = blockIdx.z;
    int tid = threadIdx.x;
    int dd = tile * 128 + tid;
    int k0 = kg * 4;
    __shared__ float sDr[4][128], sDi[4][128], sxf[128], sxl[128];

    float ck[4], sk[4];
#pragma unroll
    for (int kk = 0; kk < 4; kk++) {
        float2 t = g_tw[Mq + (k0 + kk)];
        ck[kk] = t.x; sk[kk] = -t.y;
    }
#pragma unroll
    for (int kk = 0; kk < 4; kk++) {
        float2 Dv = g_D[(size_t)(b * Mq + k0 + kk) * Dq + cc * 128 + tid];
        sDr[kk][tid] = Dv.x; sDi[kk][tid] = Dv.y;
    }
    if (kg == 0) {
        sxf[tid] = g_xsf[b * Dq + cc * 128 + tid];
        sxl[tid] = g_xsl[b * Dq + cc * 128 + tid];
    }
    __syncthreads();

    float ar[4] = {0.f,0.f,0.f,0.f}, ai[4] = {0.f,0.f,0.f,0.f};
    float a0 = 0.f, aN = 0.f;
    int dibase = cc * 128;
#pragma unroll 4
    for (int j = 0; j < 128; j++) {
        size_t o = (size_t)(dibase + j) * Dq + dd;
        float w1 = g_w1[o], ws = g_ws[o], wd = g_wd[o];
#pragma unroll
        for (int kk = 0; kk < 4; kk++) {
            float hr = fmaf(ws, ck[kk], w1);
            float hi = wd * sk[kk];
            float Dr = sDr[kk][j], Di = sDi[kk][j];
            ar[kk] = fmaf(hr, Dr, ar[kk]); ar[kk] = fmaf(-hi, Di, ar[kk]);
            ai[kk] = fmaf(hr, Di, ai[kk]); ai[kk] = fmaf( hi, Dr, ai[kk]);
        }
        if (kg == 0) {
            float w0 = 0.5f * (ws - wd), w2 = 0.5f * (ws + wd);
            a0 = fmaf(-w0, sxl[j], a0);   // circular wrap removal at s=0
            aN = fmaf(-w2, sxf[j], aN);   // circular wrap removal at s=S-1
        }
    }
#pragma unroll
    for (int kk = 0; kk < 4; kk++)
        g_c1p[((size_t)(cc * Bq + b) * Mq + k0 + kk) * Dq + dd] = make_float2(ar[kk], ai[kk]);
    if (kg == 0)
        g_edg[(size_t)(cc * Bq + b) * Dq + dd] = make_float2(a0, aN);
}

// ---------------- reduce c1 partials: A_k = sc*(conv + identity), edge sums ----------------
__global__ void c1r_k() {
    int k = blockIdx.x, b = blockIdx.y, d = threadIdx.x;
    float sr = 0.f, si = 0.f;
#pragma unroll
    for (int cc = 0; cc < 4; cc++) {
        float2 v = g_c1p[((size_t)(cc * Bq + b) * Mq + k) * Dq + d];
        sr += v.x; si += v.y;
    }
    float2 Dv = g_D[(size_t)(b * Mq + k) * Dq + d];
    float sc = (k == 0) ? INV_S : 2.f * INV_S;
    g_A[(size_t)(b * Mq + k) * Dq + d] = make_float2(sc * (sr + Dv.x), sc * (si + Dv.y));
    if (k == 0) {
        float e0 = 0.f, eN = 0.f;
#pragma unroll
        for (int cc = 0; cc < 4; cc++) {
            float2 e = g_edg[(size_t)(cc * Bq + b) * Dq + d];
            e0 += e.x; eN += e.y;
        }
        g_c0[b * Dq + d] = e0;
        g_cN[b * Dq + d] = eN;
    }
}

// ---------------- final: 2 d per thread, half-period pairing, prefetch ----------------
// out(s)      = x(s)      + cb + (pe + po)
// out(s+2048) = x(s+2048) + cb + (pe - po)
// grid (NCH, Bq), block 256
__global__ void __launch_bounds__(256) final_k(const float* __restrict__ x,
                        const float* __restrict__ cb,
                        float* __restrict__ out) {
    __shared__ ulonglong2 stw[SCH * 8];   // 4 KB
    int b = blockIdx.y, ch = blockIdx.x, t = threadIdx.x;
    int s0 = ch * SCH;
    const ulonglong2* twp = (const ulonglong2*)(g_tw + (size_t)s0 * Mq);
    stw[t] = twp[t];
    __syncthreads();

    unsigned long long a0[Mq], a1[Mq];
    const ulonglong2* Ap = (const ulonglong2*)g_A + (size_t)b * Mq * 256 + t;
#pragma unroll
    for (int k = 0; k < Mq; k++) { ulonglong2 v = Ap[k * 256]; a0[k] = v.x; a1[k] = v.y; }

    float2 base = ((const float2*)cb)[t];
    float2 c0v  = ((const float2*)g_c0)[b * 256 + t];
    float2 cNv  = ((const float2*)g_cN)[b * 256 + t];
    const float2* xa = (const float2*)(x + (size_t)(b * Sq + s0) * Dq) + t;
    const float2* xb = xa + (size_t)Hq * 256;
    float2* oa = (float2*)(out + (size_t)(b * Sq + s0) * Dq) + t;
    float2* ob = oa + (size_t)Hq * 256;

    float2 va[4], vb[4];
#pragma unroll
    for (int u = 0; u < 4; u++) { va[u] = xa[u * 256]; vb[u] = xb[u * 256]; }

#pragma unroll 1
    for (int i0 = 0; i0 < SCH; i0 += 4) {
        int ip = (i0 + 4 < SCH) ? (i0 + 4) : (SCH - 4);   // clamped prefetch
        float2 na[4], nb[4];
#pragma unroll
        for (int u = 0; u < 4; u++) { na[u] = xa[(ip + u) * 256]; nb[u] = xb[(ip + u) * 256]; }
#pragma unroll
        for (int u = 0; u < 4; u++) {
            int i = i0 + u;
            unsigned long long ae0 = 0ull, ao0 = 0ull, ae1 = 0ull, ao1 = 0ull;
#pragma unroll
            for (int k2 = 0; k2 < 8; k2++) {
                ulonglong2 tt = stw[i * 8 + k2];
                asm("fma.rn.f32x2 %0, %1, %2, %0;" : "+l"(ae0) : "l"(a0[2*k2  ]), "l"(tt.x));
                asm("fma.rn.f32x2 %0, %1, %2, %0;" : "+l"(ao0) : "l"(a0[2*k2+1]), "l"(tt.y));
                asm("fma.rn.f32x2 %0, %1, %2, %0;" : "+l"(ae1) : "l"(a1[2*k2  ]), "l"(tt.x));
                asm("fma.rn.f32x2 %0, %1, %2, %0;" : "+l"(ao1) : "l"(a1[2*k2+1]), "l"(tt.y));
            }
            float e0x, e0y, o0x, o0y, e1x, e1y, o1x, o1y;
            asm("mov.b64 {%0, %1}, %2;" : "=f"(e0x), "=f"(e0y) : "l"(ae0));
            asm("mov.b64 {%0, %1}, %2;" : "=f"(o0x), "=f"(o0y) : "l"(ao0));
            asm("mov.b64 {%0, %1}, %2;" : "=f"(e1x), "=f"(e1y) : "l"(ae1));
            asm("mov.b64 {%0, %1}, %2;" : "=f"(o1x), "=f"(o1y) : "l"(ao1));
            float pe0 = e0x + e0y, po0 = o0x + o0y;
            float pe1 = e1x + e1y, po1 = o1x + o1y;
            float2 vlo, vhi;
            vlo.x = va[u].x + base.x + (pe0 + po0);
            vhi.x = vb[u].x + base.x + (pe0 - po0);
            vlo.y = va[u].y + base.y + (pe1 + po1);
            vhi.y = vb[u].y + base.y + (pe1 - po1);
            if (ch == 0 && i == 0)             { vlo.x += c0v.x; vlo.y += c0v.y; }   // s == 0
            if (ch == NCH - 1 && i == SCH - 1) { vhi.x += cNv.x; vhi.y += cNv.y; }   // s == Sq-1
            oa[i * 256] = vlo;
            ob[i * 256] = vhi;
        }
#pragma unroll
        for (int u = 0; u < 4; u++) { va[u] = na[u]; vb[u] = nb[u]; }
    }
}

// ---------------- launch ----------------
extern "C" void kernel_launch(void* const* d_in, const int* in_sizes, int n_in,
                              void* d_out, int out_size) {
    (void)in_sizes; (void)n_in; (void)out_size;
    const float* x     = (const float*)d_in[0];
    const float* gamma = (const float*)d_in[1];
    const float* beta  = (const float*)d_in[2];
    const float* wr    = (const float*)d_in[3];
    const float* wi    = (const float*)d_in[4];
    const float* cw    = (const float*)d_in[5];
    const float* cb    = (const float*)d_in[6];
    float* out = (float*)d_out;

    twiddle_k<<<(Hq * Mq) / 256, 256>>>();
    tr_k<<<dim3(Dq / 32, Dq / 32), dim3(32, 8)>>>(cw);
    ln_k<<<(Bq * Sq) / 8, 256>>>(x);
    cmu_k<<<dim3(Mq, Bq), 256>>>();
    proj_k<<<dim3(NCH, Bq), 256>>>(x);
    c0a_k<<<dim3(Mq, Bq, 4), 128>>>(wr, wi, gamma, beta);
    c0b_k<<<Bq, Dq>>>();
    c1_k<<<dim3(16, 4, Bq), 128>>>();
    c1r_k<<<dim3(Mq, Bq), Dq>>>();
    final_k<<<dim3(NCH, Bq), 256>>>(x, cb, out);
}

// round 13
// speedup vs baseline: 1.0021x; 1.0021x over previous
#include <cuda_runtime.h>

#define Bq 8
#define Sq 4096
#define Hq 2048               // half period
#define Dq 512
#define Mq 16
#define NCH 64                // chunks for proj/final (pair-rows per chunk = 32)
#define SCH (Hq/NCH)          // 32
#define INV_S (1.0f/4096.0f)

// ---------------- device scratch (no allocations allowed) ----------------
__device__ __align__(16) float2 g_tw[Hq*Mq];   // per (s,k), s<2048: (cos(w_k s), -sin(w_k s))
__device__ float  g_mu[Bq*Sq];
__device__ float  g_rs[Bq*Sq];
__device__ __align__(16) float2 g_part[NCH*Bq*Mq*Dq]; // partial A projections [chunk][b][k][d]
__device__ float2 g_C[Bq*Mq];                  // C_k[b] = sum_s rs*mu*tw  (complex)
__device__ float2 g_D[Bq*Mq*Dq];               // spectral coeffs with w applied [b][k][d]
__device__ float  g_xsf[Bq*Dq];                // xs at s=0   (scaled by 1/S)
__device__ float  g_xsl[Bq*Dq];                // xs at s=S-1 (scaled by 1/S)
__device__ __align__(16) float2 g_A[Bq*Mq*Dq]; // combined scaled coeffs [b][k][d]
__device__ float  g_c0[Bq*Dq];                 // boundary correction at s=0
__device__ float  g_cN[Bq*Dq];                 // boundary correction at s=S-1
// transposed conv weights, [di][dd] layout (coalesced along dd)
__device__ float  g_w1[Dq*Dq];
__device__ float  g_ws[Dq*Dq];                 // w0+w2
__device__ float  g_wd[Dq*Dq];                 // w2-w0
// c1 partials over di-chunks
__device__ float2 g_c1p[4*Bq*Mq*Dq];           // [cc][b][k][dd]
__device__ float2 g_edg[4*Bq*Dq];              // [cc][b][dd] -> (a0, aN)

// ---------------- twiddle table (float sincospi: exact argument) ----------------
__global__ void twiddle_k() {
    int i = blockIdx.x * 256 + threadIdx.x;   // i = s*16 + k, s < 2048
    int s = i >> 4, k = i & 15;
    int ks = (k * s) & (Sq - 1);
    float sf, cf;
    sincospif((float)ks * (1.0f / 2048.0f), &sf, &cf);
    g_tw[i] = make_float2(cf, -sf);
}

// ---------------- transpose conv weights into [di][dd] planes ----------------
__global__ void tr_k(const float* __restrict__ cw) {
    __shared__ float t1[32][33], ts[32][33], td[32][33];
    int di0 = blockIdx.x * 32, dd0 = blockIdx.y * 32;
    int tx = threadIdx.x, ty = threadIdx.y;   // block (32,8)
#pragma unroll
    for (int jj = 0; jj < 4; jj++) {
        int ddl = ty + jj * 8;
        const float* p = cw + ((size_t)(dd0 + ddl) * Dq + di0 + tx) * 3;
        float w0 = p[0], w1 = p[1], w2 = p[2];
        t1[ddl][tx] = w1;
        ts[ddl][tx] = w0 + w2;
        td[ddl][tx] = w2 - w0;
    }
    __syncthreads();
#pragma unroll
    for (int jj = 0; jj < 4; jj++) {
        int dil = ty + jj * 8;
        size_t o = (size_t)(di0 + dil) * Dq + dd0 + tx;
        g_w1[o] = t1[tx][dil];
        g_ws[o] = ts[tx][dil];
        g_wd[o] = td[tx][dil];
    }
}

// ---------------- LayerNorm stats: one warp per (b,s) row ----------------
__global__ void ln_k(const float* __restrict__ x) {
    int lane = threadIdx.x & 31;
    int row  = blockIdx.x * 8 + (threadIdx.x >> 5);   // b*Sq + s
    const float4* xr = (const float4*)(x + (size_t)row * Dq);
    float s1 = 0.f, s2 = 0.f;
#pragma unroll
    for (int it = 0; it < 4; it++) {
        float4 v = xr[lane + it * 32];
        s1 += (v.x + v.y) + (v.z + v.w);
        s2 = fmaf(v.x, v.x, s2); s2 = fmaf(v.y, v.y, s2);
        s2 = fmaf(v.z, v.z, s2); s2 = fmaf(v.w, v.w, s2);
    }
#pragma unroll
    for (int off = 16; off > 0; off >>= 1) {
        s1 += __shfl_xor_sync(0xffffffffu, s1, off);
        s2 += __shfl_xor_sync(0xffffffffu, s2, off);
    }
    if (lane == 0) {
        float mu  = s1 * (1.f / Dq);
        float var = fmaf(-mu, mu, s2 * (1.f / Dq));
        g_mu[row] = mu;
        g_rs[row] = rsqrtf(var + 1e-5f);
    }
}

// ---------------- C_k[b] = sum_s rs*mu*tw (per-batch scalar correction) ----------------
__global__ void cmu_k() {
    int k = blockIdx.x, b = blockIdx.y, t = threadIdx.x;
    float sgn = (k & 1) ? -1.f : 1.f;
    float2 acc = make_float2(0.f, 0.f);
    for (int p = t; p < Hq; p += 256) {
        float ma = g_mu[b * Sq + p]      * g_rs[b * Sq + p];
        float mb = g_mu[b * Sq + Hq + p] * g_rs[b * Sq + Hq + p];
        float m = fmaf(sgn, mb, ma);
        float2 tw = g_tw[p * Mq + k];
        acc.x = fmaf(m, tw.x, acc.x);
        acc.y = fmaf(m, tw.y, acc.y);
    }
    __shared__ float2 red[256];
    red[t] = acc; __syncthreads();
    for (int o = 128; o > 0; o >>= 1) {
        if (t < o) { red[t].x += red[t + o].x; red[t].y += red[t + o].y; }
        __syncthreads();
    }
    if (t == 0) g_C[b * Mq + k] = red[0];
}

// ---------------- projection: A_k[b,d] = sum_s rs*x*tw, 2 d per thread ----------------
// half-period pairing; grid (NCH, Bq), block 256 (each thread owns d=2t, 2t+1)
__global__ void __launch_bounds__(256) proj_k(const float* __restrict__ x) {
    __shared__ ulonglong2 stw[SCH * 8];   // 4 KB
    __shared__ float srs[2 * SCH];
    int b = blockIdx.y, ch = blockIdx.x, t = threadIdx.x;
    int s0 = ch * SCH;
    const ulonglong2* twp = (const ulonglong2*)(g_tw + (size_t)s0 * Mq);
    stw[t] = twp[t];   // 256 entries exactly
    int row0 = b * Sq + s0;
    if (t < 2 * SCH) srs[t] = g_rs[row0 + (t < SCH ? t : Hq + (t - SCH))];
    __syncthreads();

    unsigned long long acc0[Mq], acc1[Mq];
#pragma unroll
    for (int k = 0; k < Mq; k++) { acc0[k] = 0ull; acc1[k] = 0ull; }

    const float2* xa = (const float2*)(x + (size_t)row0 * Dq) + t;   // row stride 256
    const float2* xb = xa + (size_t)Hq * 256;

    float2 va[4], vb[4];
#pragma unroll
    for (int u = 0; u < 4; u++) { va[u] = xa[u * 256]; vb[u] = xb[u * 256]; }

#pragma unroll 1
    for (int i0 = 0; i0 < SCH; i0 += 4) {
        int ip = (i0 + 4 < SCH) ? (i0 + 4) : (SCH - 4);   // clamped prefetch
        float2 na[4], nb[4];
#pragma unroll
        for (int u = 0; u < 4; u++) { na[u] = xa[(ip + u) * 256]; nb[u] = xb[(ip + u) * 256]; }
#pragma unroll
        for (int u = 0; u < 4; u++) {
            int i = i0 + u;
            float rsa = srs[i], rsb = srs[SCH + i];
            float ax = va[u].x * rsa, ay = va[u].y * rsa;
            float bx = vb[u].x * rsb, by = vb[u].y * rsb;
            float ysx = ax + bx, ydx = ax - bx;
            float ysy = ay + by, ydy = ay - by;
            unsigned long long psx, pdx, psy, pdy;
            asm("mov.b64 %0, {%1, %1};" : "=l"(psx) : "f"(ysx));
            asm("mov.b64 %0, {%1, %1};" : "=l"(pdx) : "f"(ydx));
            asm("mov.b64 %0, {%1, %1};" : "=l"(psy) : "f"(ysy));
            asm("mov.b64 %0, {%1, %1};" : "=l"(pdy) : "f"(ydy));
#pragma unroll
            for (int k2 = 0; k2 < 8; k2++) {
                ulonglong2 tt = stw[i * 8 + k2];
                asm("fma.rn.f32x2 %0, %1, %2, %0;" : "+l"(acc0[2*k2  ]) : "l"(psx), "l"(tt.x));
                asm("fma.rn.f32x2 %0, %1, %2, %0;" : "+l"(acc0[2*k2+1]) : "l"(pdx), "l"(tt.y));
                asm("fma.rn.f32x2 %0, %1, %2, %0;" : "+l"(acc1[2*k2  ]) : "l"(psy), "l"(tt.x));
                asm("fma.rn.f32x2 %0, %1, %2, %0;" : "+l"(acc1[2*k2+1]) : "l"(pdy), "l"(tt.y));
            }
        }
#pragma unroll
        for (int u = 0; u < 4; u++) { va[u] = na[u]; vb[u] = nb[u]; }
    }
    ulonglong2* pout = (ulonglong2*)g_part + ((size_t)(ch * Bq + b) * Mq) * 256 + t;
#pragma unroll
    for (int k = 0; k < Mq; k++) pout[k * 256] = make_ulonglong2(acc0[k], acc1[k]);
}

// ---------------- reduce partials, apply LN affine correction + spectral weight ----------------
__global__ void c0a_k(const float* __restrict__ wr, const float* __restrict__ wi,
                      const float* __restrict__ gamma, const float* __restrict__ beta) {
    int k = blockIdx.x, b = blockIdx.y;
    int d = blockIdx.z * 128 + threadIdx.x;
    const unsigned long long* pp = (const unsigned long long*)g_part;
    unsigned long long s = 0ull;
#pragma unroll 8
    for (int c = 0; c < NCH; c++) {
        unsigned long long v = pp[((size_t)(c * Bq + b) * Mq + k) * Dq + d];
        asm("add.rn.f32x2 %0, %0, %1;" : "+l"(s) : "l"(v));
    }
    float sr, si;
    asm("mov.b64 {%0, %1}, %2;" : "=f"(sr), "=f"(si) : "l"(s));
    float2 C = g_C[b * Mq + k];
    float gm = gamma[d], bt = beta[d];
    float Pr = gm * (sr - C.x);
    if (k == 0) Pr += 4096.f * bt;      // T_0 = S, T_k = 0 for k>0
    float Pi = gm * (si - C.y);
    float wrv = wr[d * Mq + k], wiv = wi[d * Mq + k];
    float Dr = Pr * wrv - Pi * wiv;
    float Di = (k == 0) ? 0.f : fmaf(Pr, wiv, Pi * wrv);   // irfft drops Im of bin 0
    g_D[(size_t)(b * Mq + k) * Dq + d] = make_float2(Dr, Di);
}

// ---------------- edge values xs(0), xs(S-1) ----------------
__global__ void c0b_k() {
    int b = blockIdx.x, di = threadIdx.x;
    float xsf = 0.f, xsl = 0.f;
#pragma unroll
    for (int k = 0; k < Mq; k++) {
        float2 Dv = g_D[(size_t)(b * Mq + k) * Dq + di];
        float2 t = g_tw[Mq + k];           // s=1 row: (cos w_k, -sin w_k)
        float ck = t.x, sk = -t.y;
        float m = (k == 0) ? 1.f : 2.f;
        xsf += m * Dv.x;
        xsl += m * (Dv.x * ck + Dv.y * sk);    // Re(D_k e^{-i w_k})
    }
    g_xsf[b * Dq + di] = xsf * INV_S;
    g_xsl[b * Dq + di] = xsl * INV_S;
}

// ---------------- spectral-domain conv partials: coalesced, split over di chunks ----------------
__global__ void c1_k() {
    int kg = blockIdx.x & 3, cc = blockIdx.x >> 2;
    int tile = blockIdx.y, b = blockIdx.z;
    int tid = threadIdx.x;
    int dd = tile * 128 + tid;
    int k0 = kg * 4;
    __shared__ float sDr[4][128], sDi[4][128], sxf[128], sxl[128];

    float ck[4], sk[4];
#pragma unroll
    for (int kk = 0; kk < 4; kk++) {
        float2 t = g_tw[Mq + (k0 + kk)];
        ck[kk] = t.x; sk[kk] = -t.y;
    }
#pragma unroll
    for (int kk = 0; kk < 4; kk++) {
        float2 Dv = g_D[(size_t)(b * Mq + k0 + kk) * Dq + cc * 128 + tid];
        sDr[kk][tid] = Dv.x; sDi[kk][tid] = Dv.y;
    }
    if (kg == 0) {
        sxf[tid] = g_xsf[b * Dq + cc * 128 + tid];
        sxl[tid] = g_xsl[b * Dq + cc * 128 + tid];
    }
    __syncthreads();

    float ar[4] = {0.f,0.f,0.f,0.f}, ai[4] = {0.f,0.f,0.f,0.f};
    float a0 = 0.f, aN = 0.f;
    int dibase = cc * 128;
#pragma unroll 4
    for (int j = 0; j < 128; j++) {
        size_t o = (size_t)(dibase + j) * Dq + dd;
        float w1 = g_w1[o], ws = g_ws[o], wd = g_wd[o];
#pragma unroll
        for (int kk = 0; kk < 4; kk++) {
            float hr = fmaf(ws, ck[kk], w1);
            float hi = wd * sk[kk];
            float Dr = sDr[kk][j], Di = sDi[kk][j];
            ar[kk] = fmaf(hr, Dr, ar[kk]); ar[kk] = fmaf(-hi, Di, ar[kk]);
            ai[kk] = fmaf(hr, Di, ai[kk]); ai[kk] = fmaf( hi, Dr, ai[kk]);
        }
        if (kg == 0) {
            float w0 = 0.5f * (ws - wd), w2 = 0.5f * (ws + wd);
            a0 = fmaf(-w0, sxl[j], a0);   // circular wrap removal at s=0
            aN = fmaf(-w2, sxf[j], aN);   // circular wrap removal at s=S-1
        }
    }
#pragma unroll
    for (int kk = 0; kk < 4; kk++)
        g_c1p[((size_t)(cc * Bq + b) * Mq + k0 + kk) * Dq + dd] = make_float2(ar[kk], ai[kk]);
    if (kg == 0)
        g_edg[(size_t)(cc * Bq + b) * Dq + dd] = make_float2(a0, aN);
}

// ---------------- reduce c1 partials: A_k = sc*(conv + identity), edge sums ----------------
__global__ void c1r_k() {
    int k = blockIdx.x, b = blockIdx.y, d = threadIdx.x;
    float sr = 0.f, si = 0.f;
#pragma unroll
    for (int cc = 0; cc < 4; cc++) {
        float2 v = g_c1p[((size_t)(cc * Bq + b) * Mq + k) * Dq + d];
        sr += v.x; si += v.y;
    }
    float2 Dv = g_D[(size_t)(b * Mq + k) * Dq + d];
    float sc = (k == 0) ? INV_S : 2.f * INV_S;
    g_A[(size_t)(b * Mq + k) * Dq + d] = make_float2(sc * (sr + Dv.x), sc * (si + Dv.y));
    if (k == 0) {
        float e0 = 0.f, eN = 0.f;
#pragma unroll
        for (int cc = 0; cc < 4; cc++) {
            float2 e = g_edg[(size_t)(cc * Bq + b) * Dq + d];
            e0 += e.x; eN += e.y;
        }
        g_c0[b * Dq + d] = e0;
        g_cN[b * Dq + d] = eN;
    }
}

// ---------------- final: 2 d per thread, half-period pairing, prefetch ----------------
// out(s)      = x(s)      + cb + (pe + po)
// out(s+2048) = x(s+2048) + cb + (pe - po)
// grid (NCH, Bq), block 256
__global__ void __launch_bounds__(256) final_k(const float* __restrict__ x,
                        const float* __restrict__ cb,
                        float* __restrict__ out) {
    __shared__ ulonglong2 stw[SCH * 8];   // 4 KB
    int b = blockIdx.y, ch = blockIdx.x, t = threadIdx.x;
    int s0 = ch * SCH;
    const ulonglong2* twp = (const ulonglong2*)(g_tw + (size_t)s0 * Mq);
    stw[t] = twp[t];
    __syncthreads();

    unsigned long long a0[Mq], a1[Mq];
    const ulonglong2* Ap = (const ulonglong2*)g_A + (size_t)b * Mq * 256 + t;
#pragma unroll
    for (int k = 0; k < Mq; k++) { ulonglong2 v = Ap[k * 256]; a0[k] = v.x; a1[k] = v.y; }

    float2 base = ((const float2*)cb)[t];
    float2 c0v  = ((const float2*)g_c0)[b * 256 + t];
    float2 cNv  = ((const float2*)g_cN)[b * 256 + t];
    const float2* xa = (const float2*)(x + (size_t)(b * Sq + s0) * Dq) + t;
    const float2* xb = xa + (size_t)Hq * 256;
    float2* oa = (float2*)(out + (size_t)(b * Sq + s0) * Dq) + t;
    float2* ob = oa + (size_t)Hq * 256;

    float2 va[4], vb[4];
#pragma unroll
    for (int u = 0; u < 4; u++) { va[u] = xa[u * 256]; vb[u] = xb[u * 256]; }

#pragma unroll 1
    for (int i0 = 0; i0 < SCH; i0 += 4) {
        int ip = (i0 + 4 < SCH) ? (i0 + 4) : (SCH - 4);   // clamped prefetch
        float2 na[4], nb[4];
#pragma unroll
        for (int u = 0; u < 4; u++) { na[u] = xa[(ip + u) * 256]; nb[u] = xb[(ip + u) * 256]; }
#pragma unroll
        for (int u = 0; u < 4; u++) {
            int i = i0 + u;
            unsigned long long ae0 = 0ull, ao0 = 0ull, ae1 = 0ull, ao1 = 0ull;
#pragma unroll
            for (int k2 = 0; k2 < 8; k2++) {
                ulonglong2 tt = stw[i * 8 + k2];
                asm("fma.rn.f32x2 %0, %1, %2, %0;" : "+l"(ae0) : "l"(a0[2*k2  ]), "l"(tt.x));
                asm("fma.rn.f32x2 %0, %1, %2, %0;" : "+l"(ao0) : "l"(a0[2*k2+1]), "l"(tt.y));
                asm("fma.rn.f32x2 %0, %1, %2, %0;" : "+l"(ae1) : "l"(a1[2*k2  ]), "l"(tt.x));
                asm("fma.rn.f32x2 %0, %1, %2, %0;" : "+l"(ao1) : "l"(a1[2*k2+1]), "l"(tt.y));
            }
            float e0x, e0y, o0x, o0y, e1x, e1y, o1x, o1y;
            asm("mov.b64 {%0, %1}, %2;" : "=f"(e0x), "=f"(e0y) : "l"(ae0));
            asm("mov.b64 {%0, %1}, %2;" : "=f"(o0x), "=f"(o0y) : "l"(ao0));
            asm("mov.b64 {%0, %1}, %2;" : "=f"(e1x), "=f"(e1y) : "l"(ae1));
            asm("mov.b64 {%0, %1}, %2;" : "=f"(o1x), "=f"(o1y) : "l"(ao1));
            float pe0 = e0x + e0y, po0 = o0x + o0y;
            float pe1 = e1x + e1y, po1 = o1x + o1y;
            float2 vlo, vhi;
            vlo.x = va[u].x + base.x + (pe0 + po0);
            vhi.x = vb[u].x + base.x + (pe0 - po0);
            vlo.y = va[u].y + base.y + (pe1 + po1);
            vhi.y = vb[u].y + base.y + (pe1 - po1);
            if (ch == 0 && i == 0)             { vlo.x += c0v.x; vlo.y += c0v.y; }   // s == 0
            if (ch == NCH - 1 && i == SCH - 1) { vhi.x += cNv.x; vhi.y += cNv.y; }   // s == Sq-1
            oa[i * 256] = vlo;
            ob[i * 256] = vhi;
        }
#pragma unroll
        for (int u = 0; u < 4; u++) { va[u] = na[u]; vb[u] = nb[u]; }
    }
}

// ---------------- launch ----------------
extern "C" void kernel_launch(void* const* d_in, const int* in_sizes, int n_in,
                              void* d_out, int out_size) {
    (void)in_sizes; (void)n_in; (void)out_size;
    const float* x     = (const float*)d_in[0];
    const float* gamma = (const float*)d_in[1];
    const float* beta  = (const float*)d_in[2];
    const float* wr    = (const float*)d_in[3];
    const float* wi    = (const float*)d_in[4];
    const float* cw    = (const float*)d_in[5];
    const float* cb    = (const float*)d_in[6];
    float* out = (float*)d_out;

    twiddle_k<<<(Hq * Mq) / 256, 256>>>();
    tr_k<<<dim3(Dq / 32, Dq / 32), dim3(32, 8)>>>(cw);
    ln_k<<<(Bq * Sq) / 8, 256>>>(x);
    cmu_k<<<dim3(Mq, Bq), 256>>>();
    proj_k<<<dim3(NCH, Bq), 256>>>(x);
    c0a_k<<<dim3(Mq, Bq, 4), 128>>>(wr, wi, gamma, beta);
    c0b_k<<<Bq, Dq>>>();
    c1_k<<<dim3(16, 4, Bq), 128>>>();
    c1r_k<<<dim3(Mq, Bq), Dq>>>();
    final_k<<<dim3(NCH, Bq), 256>>>(x, cb, out);
}

// round 14
// speedup vs baseline: 1.0141x; 1.0120x over previous
#include <cuda_runtime.h>

#define Bq 8
#define Sq 4096
#define Hq 2048               // half period
#define Dq 512
#define Mq 16
#define NCH 64                // chunks for proj/final (pair-rows per chunk = 32)
#define SCH (Hq/NCH)          // 32
#define INV_S (1.0f/4096.0f)

// ---------------- device scratch (no allocations allowed) ----------------
__device__ __align__(16) float2 g_tw[Hq*Mq];   // per (s,k), s<2048: (cos(w_k s), -sin(w_k s))
__device__ float  g_mu[Bq*Sq];
__device__ float  g_rs[Bq*Sq];
__device__ __align__(16) float2 g_part[NCH*Bq*Mq*Dq]; // partial A projections [chunk][b][k][d]
__device__ float2 g_C[Bq*Mq];                  // C_k[b] = sum_s rs*mu*tw  (complex)
__device__ float2 g_D[Bq*Mq*Dq];               // spectral coeffs with w applied [b][k][d]
__device__ float  g_xsf[Bq*Dq];                // xs at s=0   (scaled by 1/S)
__device__ float  g_xsl[Bq*Dq];                // xs at s=S-1 (scaled by 1/S)
__device__ __align__(16) float2 g_A[Bq*Mq*Dq]; // combined scaled coeffs [b][k][d]
__device__ float  g_c0[Bq*Dq];                 // boundary correction at s=0
__device__ float  g_cN[Bq*Dq];                 // boundary correction at s=S-1
// transposed conv weights, [di][dd] layout (coalesced along dd)
__device__ float  g_w1[Dq*Dq];
__device__ float  g_ws[Dq*Dq];                 // w0+w2
__device__ float  g_wd[Dq*Dq];                 // w2-w0
// c1 partials over di-chunks
__device__ float2 g_c1p[4*Bq*Mq*Dq];           // [cc][b][k][dd]
__device__ float2 g_edg[4*Bq*Dq];              // [cc][b][dd] -> (a0, aN)

// ---------------- twiddle table (float sincospi: exact argument) ----------------
__global__ void twiddle_k() {
    int i = blockIdx.x * 256 + threadIdx.x;   // i = s*16 + k, s < 2048
    int s = i >> 4, k = i & 15;
    int ks = (k * s) & (Sq - 1);
    float sf, cf;
    sincospif((float)ks * (1.0f / 2048.0f), &sf, &cf);
    g_tw[i] = make_float2(cf, -sf);
}

// ---------------- transpose conv weights into [di][dd] planes ----------------
__global__ void tr_k(const float* __restrict__ cw) {
    __shared__ float t1[32][33], ts[32][33], td[32][33];
    int di0 = blockIdx.x * 32, dd0 = blockIdx.y * 32;
    int tx = threadIdx.x, ty = threadIdx.y;   // block (32,8)
#pragma unroll
    for (int jj = 0; jj < 4; jj++) {
        int ddl = ty + jj * 8;
        const float* p = cw + ((size_t)(dd0 + ddl) * Dq + di0 + tx) * 3;
        float w0 = p[0], w1 = p[1], w2 = p[2];
        t1[ddl][tx] = w1;
        ts[ddl][tx] = w0 + w2;
        td[ddl][tx] = w2 - w0;
    }
    __syncthreads();
#pragma unroll
    for (int jj = 0; jj < 4; jj++) {
        int dil = ty + jj * 8;
        size_t o = (size_t)(di0 + dil) * Dq + dd0 + tx;
        g_w1[o] = t1[tx][dil];
        g_ws[o] = ts[tx][dil];
        g_wd[o] = td[tx][dil];
    }
}

// ---------------- LayerNorm stats: one warp per (b,s) row ----------------
__global__ void ln_k(const float* __restrict__ x) {
    int lane = threadIdx.x & 31;
    int row  = blockIdx.x * 8 + (threadIdx.x >> 5);   // b*Sq + s
    const float4* xr = (const float4*)(x + (size_t)row * Dq);
    float s1 = 0.f, s2 = 0.f;
#pragma unroll
    for (int it = 0; it < 4; it++) {
        float4 v = xr[lane + it * 32];
        s1 += (v.x + v.y) + (v.z + v.w);
        s2 = fmaf(v.x, v.x, s2); s2 = fmaf(v.y, v.y, s2);
        s2 = fmaf(v.z, v.z, s2); s2 = fmaf(v.w, v.w, s2);
    }
#pragma unroll
    for (int off = 16; off > 0; off >>= 1) {
        s1 += __shfl_xor_sync(0xffffffffu, s1, off);
        s2 += __shfl_xor_sync(0xffffffffu, s2, off);
    }
    if (lane == 0) {
        float mu  = s1 * (1.f / Dq);
        float var = fmaf(-mu, mu, s2 * (1.f / Dq));
        g_mu[row] = mu;
        g_rs[row] = rsqrtf(var + 1e-5f);
    }
}

// ---------------- C_k[b] = sum_s rs*mu*tw (per-batch scalar correction) ----------------
__global__ void cmu_k() {
    int k = blockIdx.x, b = blockIdx.y, t = threadIdx.x;
    float sgn = (k & 1) ? -1.f : 1.f;
    float2 acc = make_float2(0.f, 0.f);
    for (int p = t; p < Hq; p += 256) {
        float ma = g_mu[b * Sq + p]      * g_rs[b * Sq + p];
        float mb = g_mu[b * Sq + Hq + p] * g_rs[b * Sq + Hq + p];
        float m = fmaf(sgn, mb, ma);
        float2 tw = g_tw[p * Mq + k];
        acc.x = fmaf(m, tw.x, acc.x);
        acc.y = fmaf(m, tw.y, acc.y);
    }
    __shared__ float2 red[256];
    red[t] = acc; __syncthreads();
    for (int o = 128; o > 0; o >>= 1) {
        if (t < o) { red[t].x += red[t + o].x; red[t].y += red[t + o].y; }
        __syncthreads();
    }
    if (t == 0) g_C[b * Mq + k] = red[0];
}

// ---------------- projection: A_k[b,d] = sum_s rs*x*tw, 2 d per thread ----------------
// half-period pairing; grid (NCH, Bq), block 256 (each thread owns d=2t, 2t+1)
__global__ void __launch_bounds__(256) proj_k(const float* __restrict__ x) {
    __shared__ ulonglong2 stw[SCH * 8];   // 4 KB
    __shared__ float srs[2 * SCH];
    int b = blockIdx.y, ch = blockIdx.x, t = threadIdx.x;
    int s0 = ch * SCH;
    const ulonglong2* twp = (const ulonglong2*)(g_tw + (size_t)s0 * Mq);
    stw[t] = twp[t];   // 256 entries exactly
    int row0 = b * Sq + s0;
    if (t < 2 * SCH) srs[t] = g_rs[row0 + (t < SCH ? t : Hq + (t - SCH))];
    __syncthreads();

    unsigned long long acc0[Mq], acc1[Mq];
#pragma unroll
    for (int k = 0; k < Mq; k++) { acc0[k] = 0ull; acc1[k] = 0ull; }

    const float2* xa = (const float2*)(x + (size_t)row0 * Dq) + t;   // row stride 256
    const float2* xb = xa + (size_t)Hq * 256;

    float2 va[4], vb[4];
#pragma unroll
    for (int u = 0; u < 4; u++) { va[u] = xa[u * 256]; vb[u] = xb[u * 256]; }

#pragma unroll 1
    for (int i0 = 0; i0 < SCH; i0 += 4) {
        int ip = (i0 + 4 < SCH) ? (i0 + 4) : (SCH - 4);   // clamped prefetch
        float2 na[4], nb[4];
#pragma unroll
        for (int u = 0; u < 4; u++) { na[u] = xa[(ip + u) * 256]; nb[u] = xb[(ip + u) * 256]; }
#pragma unroll
        for (int u = 0; u < 4; u++) {
            int i = i0 + u;
            float rsa = srs[i], rsb = srs[SCH + i];
            float ax = va[u].x * rsa, ay = va[u].y * rsa;
            float bx = vb[u].x * rsb, by = vb[u].y * rsb;
            float ysx = ax + bx, ydx = ax - bx;
            float ysy = ay + by, ydy = ay - by;
            unsigned long long psx, pdx, psy, pdy;
            asm("mov.b64 %0, {%1, %1};" : "=l"(psx) : "f"(ysx));
            asm("mov.b64 %0, {%1, %1};" : "=l"(pdx) : "f"(ydx));
            asm("mov.b64 %0, {%1, %1};" : "=l"(psy) : "f"(ysy));
            asm("mov.b64 %0, {%1, %1};" : "=l"(pdy) : "f"(ydy));
#pragma unroll
            for (int k2 = 0; k2 < 8; k2++) {
                ulonglong2 tt = stw[i * 8 + k2];
                asm("fma.rn.f32x2 %0, %1, %2, %0;" : "+l"(acc0[2*k2  ]) : "l"(psx), "l"(tt.x));
                asm("fma.rn.f32x2 %0, %1, %2, %0;" : "+l"(acc0[2*k2+1]) : "l"(pdx), "l"(tt.y));
                asm("fma.rn.f32x2 %0, %1, %2, %0;" : "+l"(acc1[2*k2  ]) : "l"(psy), "l"(tt.x));
                asm("fma.rn.f32x2 %0, %1, %2, %0;" : "+l"(acc1[2*k2+1]) : "l"(pdy), "l"(tt.y));
            }
        }
#pragma unroll
        for (int u = 0; u < 4; u++) { va[u] = na[u]; vb[u] = nb[u]; }
    }
    ulonglong2* pout = (ulonglong2*)g_part + ((size_t)(ch * Bq + b) * Mq) * 256 + t;
#pragma unroll
    for (int k = 0; k < Mq; k++) pout[k * 256] = make_ulonglong2(acc0[k], acc1[k]);
}

// ---------------- reduce partials, apply LN affine correction + spectral weight ----------------
__global__ void c0a_k(const float* __restrict__ wr, const float* __restrict__ wi,
                      const float* __restrict__ gamma, const float* __restrict__ beta) {
    int k = blockIdx.x, b = blockIdx.y;
    int d = blockIdx.z * 128 + threadIdx.x;
    const unsigned long long* pp = (const unsigned long long*)g_part;
    unsigned long long s = 0ull;
#pragma unroll 8
    for (int c = 0; c < NCH; c++) {
        unsigned long long v = pp[((size_t)(c * Bq + b) * Mq + k) * Dq + d];
        asm("add.rn.f32x2 %0, %0, %1;" : "+l"(s) : "l"(v));
    }
    float sr, si;
    asm("mov.b64 {%0, %1}, %2;" : "=f"(sr), "=f"(si) : "l"(s));
    float2 C = g_C[b * Mq + k];
    float gm = gamma[d], bt = beta[d];
    float Pr = gm * (sr - C.x);
    if (k == 0) Pr += 4096.f * bt;      // T_0 = S, T_k = 0 for k>0
    float Pi = gm * (si - C.y);
    float wrv = wr[d * Mq + k], wiv = wi[d * Mq + k];
    float Dr = Pr * wrv - Pi * wiv;
    float Di = (k == 0) ? 0.f : fmaf(Pr, wiv, Pi * wrv);   // irfft drops Im of bin 0
    g_D[(size_t)(b * Mq + k) * Dq + d] = make_float2(Dr, Di);
}

// ---------------- edge values xs(0), xs(S-1) ----------------
__global__ void c0b_k() {
    int b = blockIdx.x, di = threadIdx.x;
    float xsf = 0.f, xsl = 0.f;
#pragma unroll
    for (int k = 0; k < Mq; k++) {
        float2 Dv = g_D[(size_t)(b * Mq + k) * Dq + di];
        float2 t = g_tw[Mq + k];           // s=1 row: (cos w_k, -sin w_k)
        float ck = t.x, sk = -t.y;
        float m = (k == 0) ? 1.f : 2.f;
        xsf += m * Dv.x;
        xsl += m * (Dv.x * ck + Dv.y * sk);    // Re(D_k e^{-i w_k})
    }
    g_xsf[b * Dq + di] = xsf * INV_S;
    g_xsl[b * Dq + di] = xsl * INV_S;
}

// ---------------- spectral-domain conv partials: coalesced, split over di chunks ----------------
__global__ void c1_k() {
    int kg = blockIdx.x & 3, cc = blockIdx.x >> 2;
    int tile = blockIdx.y, b = blockIdx.z;
    int tid = threadIdx.x;
    int dd = tile * 128 + tid;
    int k0 = kg * 4;
    __shared__ float sDr[4][128], sDi[4][128], sxf[128], sxl[128];

    float ck[4], sk[4];
#pragma unroll
    for (int kk = 0; kk < 4; kk++) {
        float2 t = g_tw[Mq + (k0 + kk)];
        ck[kk] = t.x; sk[kk] = -t.y;
    }
#pragma unroll
    for (int kk = 0; kk < 4; kk++) {
        float2 Dv = g_D[(size_t)(b * Mq + k0 + kk) * Dq + cc * 128 + tid];
        sDr[kk][tid] = Dv.x; sDi[kk][tid] = Dv.y;
    }
    if (kg == 0) {
        sxf[tid] = g_xsf[b * Dq + cc * 128 + tid];
        sxl[tid] = g_xsl[b * Dq + cc * 128 + tid];
    }
    __syncthreads();

    float ar[4] = {0.f,0.f,0.f,0.f}, ai[4] = {0.f,0.f,0.f,0.f};
    float a0 = 0.f, aN = 0.f;
    int dibase = cc * 128;
#pragma unroll 4
    for (int j = 0; j < 128; j++) {
        size_t o = (size_t)(dibase + j) * Dq + dd;
        float w1 = g_w1[o], ws = g_ws[o], wd = g_wd[o];
#pragma unroll
        for (int kk = 0; kk < 4; kk++) {
            float hr = fmaf(ws, ck[kk], w1);
            float hi = wd * sk[kk];
            float Dr = sDr[kk][j], Di = sDi[kk][j];
            ar[kk] = fmaf(hr, Dr, ar[kk]); ar[kk] = fmaf(-hi, Di, ar[kk]);
            ai[kk] = fmaf(hr, Di, ai[kk]); ai[kk] = fmaf( hi, Dr, ai[kk]);
        }
        if (kg == 0) {
            float w0 = 0.5f * (ws - wd), w2 = 0.5f * (ws + wd);
            a0 = fmaf(-w0, sxl[j], a0);   // circular wrap removal at s=0
            aN = fmaf(-w2, sxf[j], aN);   // circular wrap removal at s=S-1
        }
    }
#pragma unroll
    for (int kk = 0; kk < 4; kk++)
        g_c1p[((size_t)(cc * Bq + b) * Mq + k0 + kk) * Dq + dd] = make_float2(ar[kk], ai[kk]);
    if (kg == 0)
        g_edg[(size_t)(cc * Bq + b) * Dq + dd] = make_float2(a0, aN);
}

// ---------------- reduce c1 partials: A_k = sc*(conv + identity), edge sums ----------------
__global__ void c1r_k() {
    int k = blockIdx.x, b = blockIdx.y, d = threadIdx.x;
    float sr = 0.f, si = 0.f;
#pragma unroll
    for (int cc = 0; cc < 4; cc++) {
        float2 v = g_c1p[((size_t)(cc * Bq + b) * Mq + k) * Dq + d];
        sr += v.x; si += v.y;
    }
    float2 Dv = g_D[(size_t)(b * Mq + k) * Dq + d];
    float sc = (k == 0) ? INV_S : 2.f * INV_S;
    g_A[(size_t)(b * Mq + k) * Dq + d] = make_float2(sc * (sr + Dv.x), sc * (si + Dv.y));
    if (k == 0) {
        float e0 = 0.f, eN = 0.f;
#pragma unroll
        for (int cc = 0; cc < 4; cc++) {
            float2 e = g_edg[(size_t)(cc * Bq + b) * Dq + d];
            e0 += e.x; eN += e.y;
        }
        g_c0[b * Dq + d] = e0;
        g_cN[b * Dq + d] = eN;
    }
}

// ---------------- final: 2 d per thread, half-period pairing, prefetch ----------------
// out(s)      = x(s)      + cb + (pe + po)
// out(s+2048) = x(s+2048) + cb + (pe - po)
// grid (NCH, Bq), block 256
__global__ void __launch_bounds__(256) final_k(const float* __restrict__ x,
                        const float* __restrict__ cb,
                        float* __restrict__ out) {
    __shared__ ulonglong2 stw[SCH * 8];   // 4 KB
    int b = blockIdx.y, ch = blockIdx.x, t = threadIdx.x;
    int s0 = ch * SCH;
    const ulonglong2* twp = (const ulonglong2*)(g_tw + (size_t)s0 * Mq);
    stw[t] = twp[t];
    __syncthreads();

    unsigned long long a0[Mq], a1[Mq];
    const ulonglong2* Ap = (const ulonglong2*)g_A + (size_t)b * Mq * 256 + t;
#pragma unroll
    for (int k = 0; k < Mq; k++) { ulonglong2 v = Ap[k * 256]; a0[k] = v.x; a1[k] = v.y; }

    float2 base = ((const float2*)cb)[t];
    float2 c0v  = ((const float2*)g_c0)[b * 256 + t];
    float2 cNv  = ((const float2*)g_cN)[b * 256 + t];
    const float2* xa = (const float2*)(x + (size_t)(b * Sq + s0) * Dq) + t;
    const float2* xb = xa + (size_t)Hq * 256;
    float2* oa = (float2*)(out + (size_t)(b * Sq + s0) * Dq) + t;
    float2* ob = oa + (size_t)Hq * 256;

    float2 va[4], vb[4];
#pragma unroll
    for (int u = 0; u < 4; u++) { va[u] = xa[u * 256]; vb[u] = xb[u * 256]; }

#pragma unroll 1
    for (int i0 = 0; i0 < SCH; i0 += 4) {
        int ip = (i0 + 4 < SCH) ? (i0 + 4) : (SCH - 4);   // clamped prefetch
        float2 na[4], nb[4];
#pragma unroll
        for (int u = 0; u < 4; u++) { na[u] = xa[(ip + u) * 256]; nb[u] = xb[(ip + u) * 256]; }
#pragma unroll
        for (int u = 0; u < 4; u++) {
            int i = i0 + u;
            unsigned long long ae0 = 0ull, ao0 = 0ull, ae1 = 0ull, ao1 = 0ull;
#pragma unroll
            for (int k2 = 0; k2 < 8; k2++) {
                ulonglong2 tt = stw[i * 8 + k2];
                asm("fma.rn.f32x2 %0, %1, %2, %0;" : "+l"(ae0) : "l"(a0[2*k2  ]), "l"(tt.x));
                asm("fma.rn.f32x2 %0, %1, %2, %0;" : "+l"(ao0) : "l"(a0[2*k2+1]), "l"(tt.y));
                asm("fma.rn.f32x2 %0, %1, %2, %0;" : "+l"(ae1) : "l"(a1[2*k2  ]), "l"(tt.x));
                asm("fma.rn.f32x2 %0, %1, %2, %0;" : "+l"(ao1) : "l"(a1[2*k2+1]), "l"(tt.y));
            }
            float e0x, e0y, o0x, o0y, e1x, e1y, o1x, o1y;
            asm("mov.b64 {%0, %1}, %2;" : "=f"(e0x), "=f"(e0y) : "l"(ae0));
            asm("mov.b64 {%0, %1}, %2;" : "=f"(o0x), "=f"(o0y) : "l"(ao0));
            asm("mov.b64 {%0, %1}, %2;" : "=f"(e1x), "=f"(e1y) : "l"(ae1));
            asm("mov.b64 {%0, %1}, %2;" : "=f"(o1x), "=f"(o1y) : "l"(ao1));
            float pe0 = e0x + e0y, po0 = o0x + o0y;
            float pe1 = e1x + e1y, po1 = o1x + o1y;
            float2 vlo, vhi;
            vlo.x = va[u].x + base.x + (pe0 + po0);
            vhi.x = vb[u].x + base.x + (pe0 - po0);
            vlo.y = va[u].y + base.y + (pe1 + po1);
            vhi.y = vb[u].y + base.y + (pe1 - po1);
            if (ch == 0 && i == 0)             { vlo.x += c0v.x; vlo.y += c0v.y; }   // s == 0
            if (ch == NCH - 1 && i == SCH - 1) { vhi.x += cNv.x; vhi.y += cNv.y; }   // s == Sq-1
            oa[i * 256] = vlo;
            ob[i * 256] = vhi;
        }
#pragma unroll
        for (int u = 0; u < 4; u++) { va[u] = na[u]; vb[u] = nb[u]; }
    }
}

// ---------------- launch ----------------
extern "C" void kernel_launch(void* const* d_in, const int* in_sizes, int n_in,
                              void* d_out, int out_size) {
    (void)in_sizes; (void)n_in; (void)out_size;
    const float* x     = (const float*)d_in[0];
    const float* gamma = (const float*)d_in[1];
    const float* beta  = (const float*)d_in[2];
    const float* wr    = (const float*)d_in[3];
    const float* wi    = (const float*)d_in[4];
    const float* cw    = (const float*)d_in[5];
    const float* cb    = (const float*)d_in[6];
    float* out = (float*)d_out;

    twiddle_k<<<(Hq * Mq) / 256, 256>>>();
    tr_k<<<dim3(Dq / 32, Dq / 32), dim3(32, 8)>>>(cw);
    ln_k<<<(Bq * Sq) / 8, 256>>>(x);
    cmu_k<<<dim3(Mq, Bq), 256>>>();
    proj_k<<<dim3(NCH, Bq), 256>>>(x);
    c0a_k<<<dim3(Mq, Bq, 4), 128>>>(wr, wi, gamma, beta);
    c0b_k<<<Bq, Dq>>>();
    c1_k<<<dim3(16, 4, Bq), 128>>>();
    c1r_k<<<dim3(Mq, Bq), Dq>>>();
    final_k<<<dim3(NCH, Bq), 256>>>(x, cb, out);
}

// round 15
// speedup vs baseline: 1.1950x; 1.1783x over previous
#include <cuda_runtime.h>

#define Bq 8
#define Sq 4096
#define Hq 2048               // half period
#define Dq 512
#define Mq 16
#define NCH 32
#define SCH (Hq/NCH)          // 64 pair-rows per chunk
#define INV_S (1.0f/4096.0f)

// ---------------- device scratch (no allocations allowed) ----------------
__device__ __align__(16) float2 g_tw[Hq*Mq];   // per (s,k), s<2048: (cos(w_k s), -sin(w_k s))
__device__ float  g_mu[Bq*Sq];
__device__ float  g_rs[Bq*Sq];
__device__ __align__(16) float2 g_part[NCH*Bq*Mq*Dq]; // partial projections [chunk][b][k][d]
__device__ float2 g_D[Bq*Mq*Dq];               // spectral coeffs with w applied [b][k][d]
__device__ float  g_xsf[Bq*Dq];                // xs at s=0   (scaled by 1/S)
__device__ float  g_xsl[Bq*Dq];                // xs at s=S-1 (scaled by 1/S)
__device__ __align__(16) float2 g_A[Bq*Mq*Dq]; // combined scaled coeffs [b][k][d]
__device__ float  g_c0[Bq*Dq];                 // boundary correction at s=0
__device__ float  g_cN[Bq*Dq];                 // boundary correction at s=S-1
// transposed conv weights, [di][dd] layout (coalesced along dd)
__device__ float  g_w1[Dq*Dq];
__device__ float  g_ws[Dq*Dq];                 // w0+w2
__device__ float  g_wd[Dq*Dq];                 // w2-w0
// c1 partials over di-chunks
__device__ float2 g_c1p[4*Bq*Mq*Dq];           // [cc][b][k][dd]
__device__ float2 g_edg[4*Bq*Dq];              // [cc][b][dd] -> (a0, aN)

// ---------------- twiddle table (float sincospi: exact argument) ----------------
__global__ void twiddle_k() {
    int i = blockIdx.x * 256 + threadIdx.x;   // i = s*16 + k, s < 2048
    int s = i >> 4, k = i & 15;
    int ks = (k * s) & (Sq - 1);
    float sf, cf;
    sincospif((float)ks * (1.0f / 2048.0f), &sf, &cf);
    g_tw[i] = make_float2(cf, -sf);
}

// ---------------- transpose conv weights into [di][dd] planes ----------------
__global__ void tr_k(const float* __restrict__ cw) {
    __shared__ float t1[32][33], ts[32][33], td[32][33];
    int di0 = blockIdx.x * 32, dd0 = blockIdx.y * 32;
    int tx = threadIdx.x, ty = threadIdx.y;   // block (32,8)
#pragma unroll
    for (int jj = 0; jj < 4; jj++) {
        int ddl = ty + jj * 8;
        const float* p = cw + ((size_t)(dd0 + ddl) * Dq + di0 + tx) * 3;
        float w0 = p[0], w1 = p[1], w2 = p[2];
        t1[ddl][tx] = w1;
        ts[ddl][tx] = w0 + w2;
        td[ddl][tx] = w2 - w0;
    }
    __syncthreads();
#pragma unroll
    for (int jj = 0; jj < 4; jj++) {
        int dil = ty + jj * 8;
        size_t o = (size_t)(di0 + dil) * Dq + dd0 + tx;
        g_w1[o] = t1[tx][dil];
        g_ws[o] = ts[tx][dil];
        g_wd[o] = td[tx][dil];
    }
}

// ---------------- LayerNorm stats: one warp per (b,s) row ----------------
__global__ void ln_k(const float* __restrict__ x) {
    int lane = threadIdx.x & 31;
    int row  = blockIdx.x * 8 + (threadIdx.x >> 5);   // b*Sq + s
    const float4* xr = (const float4*)(x + (size_t)row * Dq);
    float s1 = 0.f, s2 = 0.f;
#pragma unroll
    for (int it = 0; it < 4; it++) {
        float4 v = xr[lane + it * 32];
        s1 += (v.x + v.y) + (v.z + v.w);
        s2 = fmaf(v.x, v.x, s2); s2 = fmaf(v.y, v.y, s2);
        s2 = fmaf(v.z, v.z, s2); s2 = fmaf(v.w, v.w, s2);
    }
#pragma unroll
    for (int off = 16; off > 0; off >>= 1) {
        s1 += __shfl_xor_sync(0xffffffffu, s1, off);
        s2 += __shfl_xor_sync(0xffffffffu, s2, off);
    }
    if (lane == 0) {
        float mu  = s1 * (1.f / Dq);
        float var = fmaf(-mu, mu, s2 * (1.f / Dq));
        g_mu[row] = mu;
        g_rs[row] = rsqrtf(var + 1e-5f);
    }
}

// ---------------- projection: half-period pairing, 2 d-columns per thread ----------------
// pair (s, s+2048): P_k += (xn_a + (-1)^k xn_b) * e^{-i w_k s}
// grid (NCH, Bq), block 256 (thread t owns d = 2t, 2t+1)
__global__ void __launch_bounds__(256, 2) proj_k(const float* __restrict__ x,
                       const float* __restrict__ gamma,
                       const float* __restrict__ beta) {
    __shared__ ulonglong2 stw[SCH * 8];   // 8 KB
    __shared__ float smu[2 * SCH], srs[2 * SCH];
    int b = blockIdx.y, ch = blockIdx.x, t = threadIdx.x;
    int s0 = ch * SCH;
    const ulonglong2* twp = (const ulonglong2*)(g_tw + (size_t)s0 * Mq);
#pragma unroll
    for (int i = t; i < SCH * 8; i += 256) stw[i] = twp[i];
    int row0 = b * Sq + s0;
    if (t < SCH)            { smu[t] = g_mu[row0 + t];              srs[t] = g_rs[row0 + t]; }
    else if (t < 2 * SCH)   { smu[t] = g_mu[row0 + Hq + (t - SCH)]; srs[t] = g_rs[row0 + Hq + (t - SCH)]; }
    __syncthreads();

    float2 gm = ((const float2*)gamma)[t];
    float2 bt = ((const float2*)beta)[t];
    unsigned long long acc0[Mq], acc1[Mq];
#pragma unroll
    for (int k = 0; k < Mq; k++) { acc0[k] = 0ull; acc1[k] = 0ull; }

    const float2* xa = (const float2*)(x + (size_t)row0 * Dq) + t;   // row stride 256 float2
    const float2* xb = xa + (size_t)Hq * 256;

    float2 va[4], vb[4];
#pragma unroll
    for (int u = 0; u < 4; u++) { va[u] = xa[u * 256]; vb[u] = xb[u * 256]; }

#pragma unroll 1
    for (int i0 = 0; i0 < SCH; i0 += 4) {
        int ip = (i0 + 4 < SCH) ? (i0 + 4) : (SCH - 4);   // clamped prefetch
        float2 na[4], nb[4];
#pragma unroll
        for (int u = 0; u < 4; u++) { na[u] = xa[(ip + u) * 256]; nb[u] = xb[(ip + u) * 256]; }
#pragma unroll
        for (int u = 0; u < 4; u++) {
            int i = i0 + u;
            float mua = smu[i], rsa = srs[i];
            float mub = smu[SCH + i], rsb = srs[SCH + i];
            float ax = fmaf((va[u].x - mua) * rsa, gm.x, bt.x);
            float ay = fmaf((va[u].y - mua) * rsa, gm.y, bt.y);
            float bx = fmaf((vb[u].x - mub) * rsb, gm.x, bt.x);
            float by = fmaf((vb[u].y - mub) * rsb, gm.y, bt.y);
            float ysx = ax + bx, ydx = ax - bx;
            float ysy = ay + by, ydy = ay - by;
            unsigned long long psx, pdx, psy, pdy;
            asm("mov.b64 %0, {%1, %1};" : "=l"(psx) : "f"(ysx));
            asm("mov.b64 %0, {%1, %1};" : "=l"(pdx) : "f"(ydx));
            asm("mov.b64 %0, {%1, %1};" : "=l"(psy) : "f"(ysy));
            asm("mov.b64 %0, {%1, %1};" : "=l"(pdy) : "f"(ydy));
#pragma unroll
            for (int k2 = 0; k2 < 8; k2++) {
                ulonglong2 tt = stw[i * 8 + k2];
                asm("fma.rn.f32x2 %0, %1, %2, %0;" : "+l"(acc0[2*k2  ]) : "l"(psx), "l"(tt.x));
                asm("fma.rn.f32x2 %0, %1, %2, %0;" : "+l"(acc0[2*k2+1]) : "l"(pdx), "l"(tt.y));
                asm("fma.rn.f32x2 %0, %1, %2, %0;" : "+l"(acc1[2*k2  ]) : "l"(psy), "l"(tt.x));
                asm("fma.rn.f32x2 %0, %1, %2, %0;" : "+l"(acc1[2*k2+1]) : "l"(pdy), "l"(tt.y));
            }
        }
#pragma unroll
        for (int u = 0; u < 4; u++) { va[u] = na[u]; vb[u] = nb[u]; }
    }
    ulonglong2* pout = (ulonglong2*)g_part + ((size_t)(ch * Bq + b) * Mq) * 256 + t;
#pragma unroll
    for (int k = 0; k < Mq; k++) pout[k * 256] = make_ulonglong2(acc0[k], acc1[k]);
}

// ---------------- reduce partials, apply complex spectral weight ----------------
__global__ void c0a_k(const float* __restrict__ wr, const float* __restrict__ wi) {
    int k = blockIdx.x, b = blockIdx.y;
    int d = blockIdx.z * 128 + threadIdx.x;
    const unsigned long long* pp = (const unsigned long long*)g_part;
    unsigned long long s = 0ull;
#pragma unroll
    for (int c = 0; c < NCH; c++) {
        unsigned long long v = pp[((size_t)(c * Bq + b) * Mq + k) * Dq + d];
        asm("add.rn.f32x2 %0, %0, %1;" : "+l"(s) : "l"(v));
    }
    float sr, si;
    asm("mov.b64 {%0, %1}, %2;" : "=f"(sr), "=f"(si) : "l"(s));
    float wrv = wr[d * Mq + k], wiv = wi[d * Mq + k];
    float Dr = sr * wrv - si * wiv;
    float Di = (k == 0) ? 0.f : fmaf(sr, wiv, si * wrv);   // irfft drops Im of bin 0
    g_D[(size_t)(b * Mq + k) * Dq + d] = make_float2(Dr, Di);
}

// ---------------- edge values xs(0), xs(S-1) ----------------
__global__ void c0b_k() {
    int b = blockIdx.x, di = threadIdx.x;
    float xsf = 0.f, xsl = 0.f;
#pragma unroll
    for (int k = 0; k < Mq; k++) {
        float2 Dv = g_D[(size_t)(b * Mq + k) * Dq + di];
        float2 t = g_tw[Mq + k];           // s=1 row: (cos w_k, -sin w_k)
        float ck = t.x, sk = -t.y;
        float m = (k == 0) ? 1.f : 2.f;
        xsf += m * Dv.x;
        xsl += m * (Dv.x * ck + Dv.y * sk);    // Re(D_k e^{-i w_k})
    }
    g_xsf[b * Dq + di] = xsf * INV_S;
    g_xsl[b * Dq + di] = xsl * INV_S;
}

// ---------------- spectral-domain conv partials: coalesced, split over di chunks ----------------
__global__ void c1_k() {
    int kg = blockIdx.x & 3, cc = blockIdx.x >> 2;
    int tile = blockIdx.y, b = blockIdx.z;
    int tid = threadIdx.x;
    int dd = tile * 128 + tid;
    int k0 = kg * 4;
    __shared__ float sDr[4][128], sDi[4][128], sxf[128], sxl[128];

    float ck[4], sk[4];
#pragma unroll
    for (int kk = 0; kk < 4; kk++) {
        float2 t = g_tw[Mq + (k0 + kk)];
        ck[kk] = t.x; sk[kk] = -t.y;
    }
#pragma unroll
    for (int kk = 0; kk < 4; kk++) {
        float2 Dv = g_D[(size_t)(b * Mq + k0 + kk) * Dq + cc * 128 + tid];
        sDr[kk][tid] = Dv.x; sDi[kk][tid] = Dv.y;
    }
    if (kg == 0) {
        sxf[tid] = g_xsf[b * Dq + cc * 128 + tid];
        sxl[tid] = g_xsl[b * Dq + cc * 128 + tid];
    }
    __syncthreads();

    float ar[4] = {0.f,0.f,0.f,0.f}, ai[4] = {0.f,0.f,0.f,0.f};
    float a0 = 0.f, aN = 0.f;
    int dibase = cc * 128;
#pragma unroll 4
    for (int j = 0; j < 128; j++) {
        size_t o = (size_t)(dibase + j) * Dq + dd;
        float w1 = g_w1[o], ws = g_ws[o], wd = g_wd[o];
#pragma unroll
        for (int kk = 0; kk < 4; kk++) {
            float hr = fmaf(ws, ck[kk], w1);
            float hi = wd * sk[kk];
            float Dr = sDr[kk][j], Di = sDi[kk][j];
            ar[kk] = fmaf(hr, Dr, ar[kk]); ar[kk] = fmaf(-hi, Di, ar[kk]);
            ai[kk] = fmaf(hr, Di, ai[kk]); ai[kk] = fmaf( hi, Dr, ai[kk]);
        }
        if (kg == 0) {
            float w0 = 0.5f * (ws - wd), w2 = 0.5f * (ws + wd);
            a0 = fmaf(-w0, sxl[j], a0);   // circular wrap removal at s=0
            aN = fmaf(-w2, sxf[j], aN);   // circular wrap removal at s=S-1
        }
    }
#pragma unroll
    for (int kk = 0; kk < 4; kk++)
        g_c1p[((size_t)(cc * Bq + b) * Mq + k0 + kk) * Dq + dd] = make_float2(ar[kk], ai[kk]);
    if (kg == 0)
        g_edg[(size_t)(cc * Bq + b) * Dq + dd] = make_float2(a0, aN);
}

// ---------------- reduce c1 partials: A_k = sc*(conv + identity), edge sums ----------------
__global__ void c1r_k() {
    int k = blockIdx.x, b = blockIdx.y, d = threadIdx.x;
    float sr = 0.f, si = 0.f;
#pragma unroll
    for (int cc = 0; cc < 4; cc++) {
        float2 v = g_c1p[((size_t)(cc * Bq + b) * Mq + k) * Dq + d];
        sr += v.x; si += v.y;
    }
    float2 Dv = g_D[(size_t)(b * Mq + k) * Dq + d];
    float sc = (k == 0) ? INV_S : 2.f * INV_S;
    g_A[(size_t)(b * Mq + k) * Dq + d] = make_float2(sc * (sr + Dv.x), sc * (si + Dv.y));
    if (k == 0) {
        float e0 = 0.f, eN = 0.f;
#pragma unroll
        for (int cc = 0; cc < 4; cc++) {
            float2 e = g_edg[(size_t)(cc * Bq + b) * Dq + d];
            e0 += e.x; eN += e.y;
        }
        g_c0[b * Dq + d] = e0;
        g_cN[b * Dq + d] = eN;
    }
}

// ---------------- final: half-period pairing, 2 d-columns per thread ----------------
// out(s)      = x(s)      + cb + (pe + po)
// out(s+2048) = x(s+2048) + cb + (pe - po)
// grid (NCH, Bq), block 256
__global__ void __launch_bounds__(256, 2) final_k(const float* __restrict__ x,
                        const float* __restrict__ cb,
                        float* __restrict__ out) {
    __shared__ ulonglong2 stw[SCH * 8];   // 8 KB
    int b = blockIdx.y, ch = blockIdx.x, t = threadIdx.x;
    int s0 = ch * SCH;
    const ulonglong2* twp = (const ulonglong2*)(g_tw + (size_t)s0 * Mq);
#pragma unroll
    for (int i = t; i < SCH * 8; i += 256) stw[i] = twp[i];
    __syncthreads();

    unsigned long long a0[Mq], a1[Mq];
    const ulonglong2* Ap = (const ulonglong2*)g_A + (size_t)b * Mq * 256 + t;
#pragma unroll
    for (int k = 0; k < Mq; k++) { ulonglong2 v = Ap[k * 256]; a0[k] = v.x; a1[k] = v.y; }

    float2 base = ((const float2*)cb)[t];
    float2 c0v  = ((const float2*)g_c0)[b * 256 + t];
    float2 cNv  = ((const float2*)g_cN)[b * 256 + t];
    const float2* xa = (const float2*)(x + (size_t)(b * Sq + s0) * Dq) + t;
    const float2* xb = xa + (size_t)Hq * 256;
    float2* oa = (float2*)(out + (size_t)(b * Sq + s0) * Dq) + t;
    float2* ob = oa + (size_t)Hq * 256;

    float2 va[4], vb[4];
#pragma unroll
    for (int u = 0; u < 4; u++) { va[u] = xa[u * 256]; vb[u] = xb[u * 256]; }

#pragma unroll 1
    for (int i0 = 0; i0 < SCH; i0 += 4) {
        int ip = (i0 + 4 < SCH) ? (i0 + 4) : (SCH - 4);   // clamped prefetch
        float2 na[4], nb[4];
#pragma unroll
        for (int u = 0; u < 4; u++) { na[u] = xa[(ip + u) * 256]; nb[u] = xb[(ip + u) * 256]; }
#pragma unroll
        for (int u = 0; u < 4; u++) {
            int i = i0 + u;
            unsigned long long ae0 = 0ull, ao0 = 0ull, ae1 = 0ull, ao1 = 0ull;
#pragma unroll
            for (int k2 = 0; k2 < 8; k2++) {
                ulonglong2 tt = stw[i * 8 + k2];
                asm("fma.rn.f32x2 %0, %1, %2, %0;" : "+l"(ae0) : "l"(a0[2*k2  ]), "l"(tt.x));
                asm("fma.rn.f32x2 %0, %1, %2, %0;" : "+l"(ao0) : "l"(a0[2*k2+1]), "l"(tt.y));
                asm("fma.rn.f32x2 %0, %1, %2, %0;" : "+l"(ae1) : "l"(a1[2*k2  ]), "l"(tt.x));
                asm("fma.rn.f32x2 %0, %1, %2, %0;" : "+l"(ao1) : "l"(a1[2*k2+1]), "l"(tt.y));
            }
            float e0x, e0y, o0x, o0y, e1x, e1y, o1x, o1y;
            asm("mov.b64 {%0, %1}, %2;" : "=f"(e0x), "=f"(e0y) : "l"(ae0));
            asm("mov.b64 {%0, %1}, %2;" : "=f"(o0x), "=f"(o0y) : "l"(ao0));
            asm("mov.b64 {%0, %1}, %2;" : "=f"(e1x), "=f"(e1y) : "l"(ae1));
            asm("mov.b64 {%0, %1}, %2;" : "=f"(o1x), "=f"(o1y) : "l"(ao1));
            float pe0 = e0x + e0y, po0 = o0x + o0y;
            float pe1 = e1x + e1y, po1 = o1x + o1y;
            float2 vlo, vhi;
            vlo.x = va[u].x + base.x + (pe0 + po0);
            vhi.x = vb[u].x + base.x + (pe0 - po0);
            vlo.y = va[u].y + base.y + (pe1 + po1);
            vhi.y = vb[u].y + base.y + (pe1 - po1);
            if (ch == 0 && i == 0)             { vlo.x += c0v.x; vlo.y += c0v.y; }   // s == 0
            if (ch == NCH - 1 && i == SCH - 1) { vhi.x += cNv.x; vhi.y += cNv.y; }   // s == Sq-1
            oa[i * 256] = vlo;
            ob[i * 256] = vhi;
        }
#pragma unroll
        for (int u = 0; u < 4; u++) { va[u] = na[u]; vb[u] = nb[u]; }
    }
}

// ---------------- launch ----------------
extern "C" void kernel_launch(void* const* d_in, const int* in_sizes, int n_in,
                              void* d_out, int out_size) {
    (void)in_sizes; (void)n_in; (void)out_size;
    const float* x     = (const float*)d_in[0];
    const float* gamma = (const float*)d_in[1];
    const float* beta  = (const float*)d_in[2];
    const float* wr    = (const float*)d_in[3];
    const float* wi    = (const float*)d_in[4];
    const float* cw    = (const float*)d_in[5];
    const float* cb    = (const float*)d_in[6];
    float* out = (float*)d_out;

    twiddle_k<<<(Hq * Mq) / 256, 256>>>();
    tr_k<<<dim3(Dq / 32, Dq / 32), dim3(32, 8)>>>(cw);
    ln_k<<<(Bq * Sq) / 8, 256>>>(x);
    proj_k<<<dim3(NCH, Bq), 256>>>(x, gamma, beta);
    c0a_k<<<dim3(Mq, Bq, 4), 128>>>(wr, wi);
    c0b_k<<<Bq, Dq>>>();
    c1_k<<<dim3(16, 4, Bq), 128>>>();
    c1r_k<<<dim3(Mq, Bq), Dq>>>();
    final_k<<<dim3(NCH, Bq), 256>>>(x, cb, out);
}

// round 16
// speedup vs baseline: 1.2114x; 1.0137x over previous
#include <cuda_runtime.h>

#define Bq 8
#define Sq 4096
#define Hq 2048               // half period
#define Dq 512
#define Mq 16
#define NCH 32
#define SCH (Hq/NCH)          // 64 pair-rows per chunk
#define INV_S (1.0f/4096.0f)

// ---------------- device scratch (no allocations allowed) ----------------
__device__ __align__(16) float2 g_tw[Hq*Mq];   // per (s,k), s<2048: (cos(w_k s), -sin(w_k s))
__device__ float  g_mu[Bq*Sq];
__device__ float  g_rs[Bq*Sq];
__device__ __align__(16) float2 g_part[NCH*Bq*Mq*Dq]; // partial projections [chunk][b][k][d]
__device__ float2 g_D[Bq*Mq*Dq];               // spectral coeffs with w applied [b][k][d]
__device__ float  g_xsf[Bq*Dq];                // xs at s=0   (scaled by 1/S)
__device__ float  g_xsl[Bq*Dq];                // xs at s=S-1 (scaled by 1/S)
__device__ __align__(16) float2 g_A[Bq*Mq*Dq]; // combined scaled coeffs [b][k][d]
__device__ float  g_c0[Bq*Dq];                 // boundary correction at s=0
__device__ float  g_cN[Bq*Dq];                 // boundary correction at s=S-1
// transposed conv weights, [di][dd] layout (coalesced along dd)
__device__ float  g_w1[Dq*Dq];
__device__ float  g_ws[Dq*Dq];                 // w0+w2
__device__ float  g_wd[Dq*Dq];                 // w2-w0
// c1 partials over di-chunks
__device__ float2 g_c1p[4*Bq*Mq*Dq];           // [cc][b][k][dd]
__device__ float2 g_edg[4*Bq*Dq];              // [cc][b][dd] -> (a0, aN)

// ---------------- twiddle table (float sincospi: exact argument) ----------------
__global__ void twiddle_k() {
    int i = blockIdx.x * 256 + threadIdx.x;   // i = s*16 + k, s < 2048
    int s = i >> 4, k = i & 15;
    int ks = (k * s) & (Sq - 1);
    float sf, cf;
    sincospif((float)ks * (1.0f / 2048.0f), &sf, &cf);
    g_tw[i] = make_float2(cf, -sf);
}

// ---------------- transpose conv weights into [di][dd] planes ----------------
__global__ void tr_k(const float* __restrict__ cw) {
    __shared__ float t1[32][33], ts[32][33], td[32][33];
    int di0 = blockIdx.x * 32, dd0 = blockIdx.y * 32;
    int tx = threadIdx.x, ty = threadIdx.y;   // block (32,8)
#pragma unroll
    for (int jj = 0; jj < 4; jj++) {
        int ddl = ty + jj * 8;
        const float* p = cw + ((size_t)(dd0 + ddl) * Dq + di0 + tx) * 3;
        float w0 = p[0], w1 = p[1], w2 = p[2];
        t1[ddl][tx] = w1;
        ts[ddl][tx] = w0 + w2;
        td[ddl][tx] = w2 - w0;
    }
    __syncthreads();
#pragma unroll
    for (int jj = 0; jj < 4; jj++) {
        int dil = ty + jj * 8;
        size_t o = (size_t)(di0 + dil) * Dq + dd0 + tx;
        g_w1[o] = t1[tx][dil];
        g_ws[o] = ts[tx][dil];
        g_wd[o] = td[tx][dil];
    }
}

// ---------------- LayerNorm stats: one warp per (b,s) row ----------------
__global__ void ln_k(const float* __restrict__ x) {
    int lane = threadIdx.x & 31;
    int row  = blockIdx.x * 8 + (threadIdx.x >> 5);   // b*Sq + s
    const float4* xr = (const float4*)(x + (size_t)row * Dq);
    float s1 = 0.f, s2 = 0.f;
#pragma unroll
    for (int it = 0; it < 4; it++) {
        float4 v = xr[lane + it * 32];
        s1 += (v.x + v.y) + (v.z + v.w);
        s2 = fmaf(v.x, v.x, s2); s2 = fmaf(v.y, v.y, s2);
        s2 = fmaf(v.z, v.z, s2); s2 = fmaf(v.w, v.w, s2);
    }
#pragma unroll
    for (int off = 16; off > 0; off >>= 1) {
        s1 += __shfl_xor_sync(0xffffffffu, s1, off);
        s2 += __shfl_xor_sync(0xffffffffu, s2, off);
    }
    if (lane == 0) {
        float mu  = s1 * (1.f / Dq);
        float var = fmaf(-mu, mu, s2 * (1.f / Dq));
        g_mu[row] = mu;
        g_rs[row] = rsqrtf(var + 1e-5f);
    }
}

// ---------------- projection: half-period pairing, 2 d-columns per thread ----------------
// pair (s, s+2048): P_k += (xn_a + (-1)^k xn_b) * e^{-i w_k s}
// grid (NCH, Bq), block 256 (thread t owns d = 2t, 2t+1)
__global__ void __launch_bounds__(256, 2) proj_k(const float* __restrict__ x,
                       const float* __restrict__ gamma,
                       const float* __restrict__ beta) {
    __shared__ ulonglong2 stw[SCH * 8];   // 8 KB
    __shared__ float smu[2 * SCH], srs[2 * SCH];
    int b = blockIdx.y, ch = blockIdx.x, t = threadIdx.x;
    int s0 = ch * SCH;
    const ulonglong2* twp = (const ulonglong2*)(g_tw + (size_t)s0 * Mq);
#pragma unroll
    for (int i = t; i < SCH * 8; i += 256) stw[i] = twp[i];
    int row0 = b * Sq + s0;
    if (t < SCH)            { smu[t] = g_mu[row0 + t];              srs[t] = g_rs[row0 + t]; }
    else if (t < 2 * SCH)   { smu[t] = g_mu[row0 + Hq + (t - SCH)]; srs[t] = g_rs[row0 + Hq + (t - SCH)]; }
    __syncthreads();

    float2 gm = ((const float2*)gamma)[t];
    float2 bt = ((const float2*)beta)[t];
    unsigned long long acc0[Mq], acc1[Mq];
#pragma unroll
    for (int k = 0; k < Mq; k++) { acc0[k] = 0ull; acc1[k] = 0ull; }

    const float2* xa = (const float2*)(x + (size_t)row0 * Dq) + t;   // row stride 256 float2
    const float2* xb = xa + (size_t)Hq * 256;

    float2 va[4], vb[4];
#pragma unroll
    for (int u = 0; u < 4; u++) { va[u] = xa[u * 256]; vb[u] = xb[u * 256]; }

#pragma unroll 1
    for (int i0 = 0; i0 < SCH; i0 += 4) {
        int ip = (i0 + 4 < SCH) ? (i0 + 4) : (SCH - 4);   // clamped prefetch
        float2 na[4], nb[4];
#pragma unroll
        for (int u = 0; u < 4; u++) { na[u] = xa[(ip + u) * 256]; nb[u] = xb[(ip + u) * 256]; }
#pragma unroll
        for (int u = 0; u < 4; u++) {
            int i = i0 + u;
            float mua = smu[i], rsa = srs[i];
            float mub = smu[SCH + i], rsb = srs[SCH + i];
            float ax = fmaf((va[u].x - mua) * rsa, gm.x, bt.x);
            float ay = fmaf((va[u].y - mua) * rsa, gm.y, bt.y);
            float bx = fmaf((vb[u].x - mub) * rsb, gm.x, bt.x);
            float by = fmaf((vb[u].y - mub) * rsb, gm.y, bt.y);
            float ysx = ax + bx, ydx = ax - bx;
            float ysy = ay + by, ydy = ay - by;
            unsigned long long psx, pdx, psy, pdy;
            asm("mov.b64 %0, {%1, %1};" : "=l"(psx) : "f"(ysx));
            asm("mov.b64 %0, {%1, %1};" : "=l"(pdx) : "f"(ydx));
            asm("mov.b64 %0, {%1, %1};" : "=l"(psy) : "f"(ysy));
            asm("mov.b64 %0, {%1, %1};" : "=l"(pdy) : "f"(ydy));
#pragma unroll
            for (int k2 = 0; k2 < 8; k2++) {
                ulonglong2 tt = stw[i * 8 + k2];
                asm("fma.rn.f32x2 %0, %1, %2, %0;" : "+l"(acc0[2*k2  ]) : "l"(psx), "l"(tt.x));
                asm("fma.rn.f32x2 %0, %1, %2, %0;" : "+l"(acc0[2*k2+1]) : "l"(pdx), "l"(tt.y));
                asm("fma.rn.f32x2 %0, %1, %2, %0;" : "+l"(acc1[2*k2  ]) : "l"(psy), "l"(tt.x));
                asm("fma.rn.f32x2 %0, %1, %2, %0;" : "+l"(acc1[2*k2+1]) : "l"(pdy), "l"(tt.y));
            }
        }
#pragma unroll
        for (int u = 0; u < 4; u++) { va[u] = na[u]; vb[u] = nb[u]; }
    }
    ulonglong2* pout = (ulonglong2*)g_part + ((size_t)(ch * Bq + b) * Mq) * 256 + t;
#pragma unroll
    for (int k = 0; k < Mq; k++) pout[k * 256] = make_ulonglong2(acc0[k], acc1[k]);
}

// ---------------- reduce partials, apply complex spectral weight ----------------
__global__ void c0a_k(const float* __restrict__ wr, const float* __restrict__ wi) {
    int k = blockIdx.x, b = blockIdx.y;
    int d = blockIdx.z * 128 + threadIdx.x;
    const unsigned long long* pp = (const unsigned long long*)g_part;
    unsigned long long s = 0ull;
#pragma unroll
    for (int c = 0; c < NCH; c++) {
        unsigned long long v = pp[((size_t)(c * Bq + b) * Mq + k) * Dq + d];
        asm("add.rn.f32x2 %0, %0, %1;" : "+l"(s) : "l"(v));
    }
    float sr, si;
    asm("mov.b64 {%0, %1}, %2;" : "=f"(sr), "=f"(si) : "l"(s));
    float wrv = wr[d * Mq + k], wiv = wi[d * Mq + k];
    float Dr = sr * wrv - si * wiv;
    float Di = (k == 0) ? 0.f : fmaf(sr, wiv, si * wrv);   // irfft drops Im of bin 0
    g_D[(size_t)(b * Mq + k) * Dq + d] = make_float2(Dr, Di);
}

// ---------------- edge values xs(0), xs(S-1) ----------------
__global__ void c0b_k() {
    int b = blockIdx.x, di = threadIdx.x;
    float xsf = 0.f, xsl = 0.f;
#pragma unroll
    for (int k = 0; k < Mq; k++) {
        float2 Dv = g_D[(size_t)(b * Mq + k) * Dq + di];
        float2 t = g_tw[Mq + k];           // s=1 row: (cos w_k, -sin w_k)
        float ck = t.x, sk = -t.y;
        float m = (k == 0) ? 1.f : 2.f;
        xsf += m * Dv.x;
        xsl += m * (Dv.x * ck + Dv.y * sk);    // Re(D_k e^{-i w_k})
    }
    g_xsf[b * Dq + di] = xsf * INV_S;
    g_xsl[b * Dq + di] = xsl * INV_S;
}

// ---------------- spectral-domain conv partials: coalesced, split over di chunks ----------------
__global__ void c1_k() {
    int kg = blockIdx.x & 3, cc = blockIdx.x >> 2;
    int tile = blockIdx.y, b = blockIdx.z;
    int tid = threadIdx.x;
    int dd = tile * 128 + tid;
    int k0 = kg * 4;
    __shared__ float sDr[4][128], sDi[4][128], sxf[128], sxl[128];

    float ck[4], sk[4];
#pragma unroll
    for (int kk = 0; kk < 4; kk++) {
        float2 t = g_tw[Mq + (k0 + kk)];
        ck[kk] = t.x; sk[kk] = -t.y;
    }
#pragma unroll
    for (int kk = 0; kk < 4; kk++) {
        float2 Dv = g_D[(size_t)(b * Mq + k0 + kk) * Dq + cc * 128 + tid];
        sDr[kk][tid] = Dv.x; sDi[kk][tid] = Dv.y;
    }
    if (kg == 0) {
        sxf[tid] = g_xsf[b * Dq + cc * 128 + tid];
        sxl[tid] = g_xsl[b * Dq + cc * 128 + tid];
    }
    __syncthreads();

    float ar[4] = {0.f,0.f,0.f,0.f}, ai[4] = {0.f,0.f,0.f,0.f};
    float a0 = 0.f, aN = 0.f;
    int dibase = cc * 128;
#pragma unroll 4
    for (int j = 0; j < 128; j++) {
        size_t o = (size_t)(dibase + j) * Dq + dd;
        float w1 = g_w1[o], ws = g_ws[o], wd = g_wd[o];
#pragma unroll
        for (int kk = 0; kk < 4; kk++) {
            float hr = fmaf(ws, ck[kk], w1);
            float hi = wd * sk[kk];
            float Dr = sDr[kk][j], Di = sDi[kk][j];
            ar[kk] = fmaf(hr, Dr, ar[kk]); ar[kk] = fmaf(-hi, Di, ar[kk]);
            ai[kk] = fmaf(hr, Di, ai[kk]); ai[kk] = fmaf( hi, Dr, ai[kk]);
        }
        if (kg == 0) {
            float w0 = 0.5f * (ws - wd), w2 = 0.5f * (ws + wd);
            a0 = fmaf(-w0, sxl[j], a0);   // circular wrap removal at s=0
            aN = fmaf(-w2, sxf[j], aN);   // circular wrap removal at s=S-1
        }
    }
#pragma unroll
    for (int kk = 0; kk < 4; kk++)
        g_c1p[((size_t)(cc * Bq + b) * Mq + k0 + kk) * Dq + dd] = make_float2(ar[kk], ai[kk]);
    if (kg == 0)
        g_edg[(size_t)(cc * Bq + b) * Dq + dd] = make_float2(a0, aN);
}

// ---------------- reduce c1 partials: A_k = sc*(conv + identity), edge sums ----------------
__global__ void c1r_k() {
    int k = blockIdx.x, b = blockIdx.y, d = threadIdx.x;
    float sr = 0.f, si = 0.f;
#pragma unroll
    for (int cc = 0; cc < 4; cc++) {
        float2 v = g_c1p[((size_t)(cc * Bq + b) * Mq + k) * Dq + d];
        sr += v.x; si += v.y;
    }
    float2 Dv = g_D[(size_t)(b * Mq + k) * Dq + d];
    float sc = (k == 0) ? INV_S : 2.f * INV_S;
    g_A[(size_t)(b * Mq + k) * Dq + d] = make_float2(sc * (sr + Dv.x), sc * (si + Dv.y));
    if (k == 0) {
        float e0 = 0.f, eN = 0.f;
#pragma unroll
        for (int cc = 0; cc < 4; cc++) {
            float2 e = g_edg[(size_t)(cc * Bq + b) * Dq + d];
            e0 += e.x; eN += e.y;
        }
        g_c0[b * Dq + d] = e0;
        g_cN[b * Dq + d] = eN;
    }
}

// ---------------- final: half-period pairing, 2 d-columns per thread ----------------
// out(s)      = x(s)      + cb + (pe + po)
// out(s+2048) = x(s+2048) + cb + (pe - po)
// grid (NCH, Bq), block 256
__global__ void __launch_bounds__(256, 2) final_k(const float* __restrict__ x,
                        const float* __restrict__ cb,
                        float* __restrict__ out) {
    __shared__ ulonglong2 stw[SCH * 8];   // 8 KB
    int b = blockIdx.y, ch = blockIdx.x, t = threadIdx.x;
    int s0 = ch * SCH;
    const ulonglong2* twp = (const ulonglong2*)(g_tw + (size_t)s0 * Mq);
#pragma unroll
    for (int i = t; i < SCH * 8; i += 256) stw[i] = twp[i];
    __syncthreads();

    unsigned long long a0[Mq], a1[Mq];
    const ulonglong2* Ap = (const ulonglong2*)g_A + (size_t)b * Mq * 256 + t;
#pragma unroll
    for (int k = 0; k < Mq; k++) { ulonglong2 v = Ap[k * 256]; a0[k] = v.x; a1[k] = v.y; }

    float2 base = ((const float2*)cb)[t];
    float2 c0v  = ((const float2*)g_c0)[b * 256 + t];
    float2 cNv  = ((const float2*)g_cN)[b * 256 + t];
    const float2* xa = (const float2*)(x + (size_t)(b * Sq + s0) * Dq) + t;
    const float2* xb = xa + (size_t)Hq * 256;
    float2* oa = (float2*)(out + (size_t)(b * Sq + s0) * Dq) + t;
    float2* ob = oa + (size_t)Hq * 256;

    float2 va[4], vb[4];
#pragma unroll
    for (int u = 0; u < 4; u++) { va[u] = xa[u * 256]; vb[u] = xb[u * 256]; }

#pragma unroll 1
    for (int i0 = 0; i0 < SCH; i0 += 4) {
        int ip = (i0 + 4 < SCH) ? (i0 + 4) : (SCH - 4);   // clamped prefetch
        float2 na[4], nb[4];
#pragma unroll
        for (int u = 0; u < 4; u++) { na[u] = xa[(ip + u) * 256]; nb[u] = xb[(ip + u) * 256]; }
#pragma unroll
        for (int u = 0; u < 4; u++) {
            int i = i0 + u;
            unsigned long long ae0 = 0ull, ao0 = 0ull, ae1 = 0ull, ao1 = 0ull;
#pragma unroll
            for (int k2 = 0; k2 < 8; k2++) {
                ulonglong2 tt = stw[i * 8 + k2];
                asm("fma.rn.f32x2 %0, %1, %2, %0;" : "+l"(ae0) : "l"(a0[2*k2  ]), "l"(tt.x));
                asm("fma.rn.f32x2 %0, %1, %2, %0;" : "+l"(ao0) : "l"(a0[2*k2+1]), "l"(tt.y));
                asm("fma.rn.f32x2 %0, %1, %2, %0;" : "+l"(ae1) : "l"(a1[2*k2  ]), "l"(tt.x));
                asm("fma.rn.f32x2 %0, %1, %2, %0;" : "+l"(ao1) : "l"(a1[2*k2+1]), "l"(tt.y));
            }
            float e0x, e0y, o0x, o0y, e1x, e1y, o1x, o1y;
            asm("mov.b64 {%0, %1}, %2;" : "=f"(e0x), "=f"(e0y) : "l"(ae0));
            asm("mov.b64 {%0, %1}, %2;" : "=f"(o0x), "=f"(o0y) : "l"(ao0));
            asm("mov.b64 {%0, %1}, %2;" : "=f"(e1x), "=f"(e1y) : "l"(ae1));
            asm("mov.b64 {%0, %1}, %2;" : "=f"(o1x), "=f"(o1y) : "l"(ao1));
            float pe0 = e0x + e0y, po0 = o0x + o0y;
            float pe1 = e1x + e1y, po1 = o1x + o1y;
            float2 vlo, vhi;
            vlo.x = va[u].x + base.x + (pe0 + po0);
            vhi.x = vb[u].x + base.x + (pe0 - po0);
            vlo.y = va[u].y + base.y + (pe1 + po1);
            vhi.y = vb[u].y + base.y + (pe1 - po1);
            if (ch == 0 && i == 0)             { vlo.x += c0v.x; vlo.y += c0v.y; }   // s == 0
            if (ch == NCH - 1 && i == SCH - 1) { vhi.x += cNv.x; vhi.y += cNv.y; }   // s == Sq-1
            oa[i * 256] = vlo;
            ob[i * 256] = vhi;
        }
#pragma unroll
        for (int u = 0; u < 4; u++) { va[u] = na[u]; vb[u] = nb[u]; }
    }
}

// ---------------- launch ----------------
extern "C" void kernel_launch(void* const* d_in, const int* in_sizes, int n_in,
                              void* d_out, int out_size) {
    (void)in_sizes; (void)n_in; (void)out_size;
    const float* x     = (const float*)d_in[0];
    const float* gamma = (const float*)d_in[1];
    const float* beta  = (const float*)d_in[2];
    const float* wr    = (const float*)d_in[3];
    const float* wi    = (const float*)d_in[4];
    const float* cw    = (const float*)d_in[5];
    const float* cb    = (const float*)d_in[6];
    float* out = (float*)d_out;

    twiddle_k<<<(Hq * Mq) / 256, 256>>>();
    tr_k<<<dim3(Dq / 32, Dq / 32), dim3(32, 8)>>>(cw);
    ln_k<<<(Bq * Sq) / 8, 256>>>(x);
    proj_k<<<dim3(NCH, Bq), 256>>>(x, gamma, beta);
    c0a_k<<<dim3(Mq, Bq, 4), 128>>>(wr, wi);
    c0b_k<<<Bq, Dq>>>();
    c1_k<<<dim3(16, 4, Bq), 128>>>();
    c1r_k<<<dim3(Mq, Bq), Dq>>>();
    final_k<<<dim3(NCH, Bq), 256>>>(x, cb, out);
}